// round 1
// baseline (speedup 1.0000x reference)
#include <cuda_runtime.h>
#include <cstdint>

#define T_TOKENS 4096
#define DM 1024
#define DH 4096
#define NE 8

// ---------------- scratch (device globals; no allocations allowed) ----------
__device__ int   g_cnt[NE];
__device__ int   g_base[NE];
__device__ float g_probsum[NE];
__device__ int   g_idx[NE * T_TOKENS];          // token id per (expert, slot)
__device__ int   g_tok_e[T_TOKENS * 2];
__device__ int   g_tok_slot[T_TOKENS * 2];
__device__ float g_tok_w[T_TOKENS * 2];
__device__ float g_H[(size_t)2 * T_TOKENS * DH];  // 8192 x 4096 hidden scratch
__device__ float g_Y[(size_t)2 * T_TOKENS * DM];  // 8192 x 1024 expert-out scratch

// ---------------- helpers ----------------------------------------------------
__device__ __forceinline__ uint32_t f2tf32(float f) {
    uint32_t r;
    asm("cvt.rna.tf32.f32 %0, %1;" : "=r"(r) : "f"(f));
    return r;
}
__device__ __forceinline__ float tfpack(float f) {
    return __uint_as_float(f2tf32(f));
}
__device__ __forceinline__ void mma8(float c[4], const uint32_t a[4],
                                     uint32_t b0, uint32_t b1) {
    asm("mma.sync.aligned.m16n8k8.row.col.f32.tf32.tf32.f32 "
        "{%0,%1,%2,%3}, {%4,%5,%6,%7}, {%8,%9}, {%0,%1,%2,%3};"
        : "+f"(c[0]), "+f"(c[1]), "+f"(c[2]), "+f"(c[3])
        : "r"(a[0]), "r"(a[1]), "r"(a[2]), "r"(a[3]), "r"(b0), "r"(b1));
}

// ---------------- kernel 0: reset counters (graph replays!) ------------------
__global__ void init_kernel() {
    int i = threadIdx.x;
    if (i < NE) { g_cnt[i] = 0; g_probsum[i] = 0.0f; }
}

// ---------------- kernel 1: router (1 warp / token) --------------------------
__global__ __launch_bounds__(256) void router_kernel(
    const float* __restrict__ x, const float* __restrict__ rw,
    const float* __restrict__ rb)
{
    int gwarp = (blockIdx.x * blockDim.x + threadIdx.x) >> 5;
    int lane = threadIdx.x & 31;
    if (gwarp >= T_TOKENS) return;
    const float* xr = x + (size_t)gwarp * DM;

    float acc[NE];
#pragma unroll
    for (int e = 0; e < NE; e++) acc[e] = 0.0f;

    for (int k0 = 0; k0 < DM; k0 += 32) {
        float xv = xr[k0 + lane];
        const float* r = rw + (size_t)(k0 + lane) * NE;
        float4 r0 = *(const float4*)r;
        float4 r1 = *(const float4*)(r + 4);
        acc[0] += xv * r0.x; acc[1] += xv * r0.y;
        acc[2] += xv * r0.z; acc[3] += xv * r0.w;
        acc[4] += xv * r1.x; acc[5] += xv * r1.y;
        acc[6] += xv * r1.z; acc[7] += xv * r1.w;
    }
#pragma unroll
    for (int e = 0; e < NE; e++) {
#pragma unroll
        for (int off = 16; off > 0; off >>= 1)
            acc[e] += __shfl_xor_sync(0xffffffffu, acc[e], off);
    }
    if (lane == 0) {
        float l[NE], p[NE];
        float m = -1e30f;
#pragma unroll
        for (int e = 0; e < NE; e++) { l[e] = acc[e] + rb[e]; m = fmaxf(m, l[e]); }
        float s = 0.0f;
#pragma unroll
        for (int e = 0; e < NE; e++) { p[e] = expf(l[e] - m); s += p[e]; }
        float inv = 1.0f / s;
#pragma unroll
        for (int e = 0; e < NE; e++) {
            p[e] *= inv;
            atomicAdd(&g_probsum[e], p[e]);
        }
        // top-2, ties resolved to earlier index (matches lax.top_k)
        int i1 = 0; float p1 = p[0];
        int i2 = -1; float p2 = -1.0f;
#pragma unroll
        for (int e = 1; e < NE; e++) {
            if (p[e] > p1) { p2 = p1; i2 = i1; p1 = p[e]; i1 = e; }
            else if (p[e] > p2) { p2 = p[e]; i2 = e; }
        }
        int s1 = atomicAdd(&g_cnt[i1], 1);
        g_idx[i1 * T_TOKENS + s1] = gwarp;
        int s2 = atomicAdd(&g_cnt[i2], 1);
        g_idx[i2 * T_TOKENS + s2] = gwarp;
        g_tok_e[2 * gwarp + 0] = i1; g_tok_slot[2 * gwarp + 0] = s1; g_tok_w[2 * gwarp + 0] = p1;
        g_tok_e[2 * gwarp + 1] = i2; g_tok_slot[2 * gwarp + 1] = s2; g_tok_w[2 * gwarp + 1] = p2;
    }
}

// ---------------- kernel 2: scan + lb_loss -----------------------------------
__global__ void finalize_kernel(float* __restrict__ out) {
    if (threadIdx.x == 0 && blockIdx.x == 0) {
        int base = 0;
        float lb = 0.0f;
        for (int e = 0; e < NE; e++) {
            g_base[e] = base;
            base += g_cnt[e];
            float f_i = (float)g_cnt[e] / (float)T_TOKENS;
            float P_i = g_probsum[e] / (float)T_TOKENS;
            lb += f_i * P_i;
        }
        out[(size_t)T_TOKENS * DM] = 0.01f * (float)NE * lb;
    }
}

// ---------------- kernel 3: FFN-in  (gathered, dual-B, SiLU gate) ------------
// Block tile: 128(M rows of one expert) x 64(N of hidden) x K=1024, BK=16.
// 8 warps, each 32x32 warptile -> 2 m16-frags x 4 n8-frags, dual accumulators.
__global__ __launch_bounds__(256) void ffn_in_kernel(
    const float* __restrict__ x,
    const float* __restrict__ w1, const float* __restrict__ b1,
    const float* __restrict__ w2, const float* __restrict__ b2)
{
    const int e = blockIdx.z;
    const int cnt = g_cnt[e];
    const int row0 = blockIdx.y * 128;
    if (row0 >= cnt) return;
    const int n0 = blockIdx.x * 64;
    const int base = g_base[e];

    __shared__ float As[2][128][20];   // [m][k], stride 20 -> conflict-free frags
    __shared__ float B1s[2][16][72];   // [k][n], stride 72
    __shared__ float B2s[2][16][72];
    __shared__ int toks[128];

    const int tid = threadIdx.x;
    if (tid < 128) {
        int r = row0 + tid;
        if (r >= cnt) r = cnt - 1;
        toks[tid] = g_idx[e * T_TOKENS + r];
    }
    __syncthreads();

    const int lane = tid & 31;
    const int wid = tid >> 5;
    const int wm = (wid & 3) * 32;
    const int wn = (wid >> 2) * 32;
    const int g = lane >> 2;
    const int tg = lane & 3;

    const float* w1e = w1 + (size_t)e * DM * DH;
    const float* w2e = w2 + (size_t)e * DM * DH;

    float c1[2][4][4], c2[2][4][4];
#pragma unroll
    for (int i = 0; i < 2; i++)
#pragma unroll
        for (int j = 0; j < 4; j++)
#pragma unroll
            for (int q = 0; q < 4; q++) { c1[i][j][q] = 0.0f; c2[i][j][q] = 0.0f; }

    // staging geometry
    const int amRow0 = tid >> 2;            // 0..63
    const int amRow1 = (tid + 256) >> 2;    // 64..127
    const int akv = (tid & 3) * 4;
    const int bk = tid >> 4;                // 0..15
    const int bnv = (tid & 15) * 4;
    const size_t aOff0 = (size_t)toks[amRow0] * DM + akv;
    const size_t aOff1 = (size_t)toks[amRow1] * DM + akv;

    float4 pA0, pA1, pB1, pB2;

    auto ldg_stage = [&](int kb) {
        pA0 = *(const float4*)(x + aOff0 + kb * 16);
        pA1 = *(const float4*)(x + aOff1 + kb * 16);
        pB1 = *(const float4*)(w1e + (size_t)(kb * 16 + bk) * DH + n0 + bnv);
        pB2 = *(const float4*)(w2e + (size_t)(kb * 16 + bk) * DH + n0 + bnv);
    };
    auto sts_stage = [&](int buf) {
        As[buf][amRow0][akv + 0] = tfpack(pA0.x);
        As[buf][amRow0][akv + 1] = tfpack(pA0.y);
        As[buf][amRow0][akv + 2] = tfpack(pA0.z);
        As[buf][amRow0][akv + 3] = tfpack(pA0.w);
        As[buf][amRow1][akv + 0] = tfpack(pA1.x);
        As[buf][amRow1][akv + 1] = tfpack(pA1.y);
        As[buf][amRow1][akv + 2] = tfpack(pA1.z);
        As[buf][amRow1][akv + 3] = tfpack(pA1.w);
        B1s[buf][bk][bnv + 0] = tfpack(pB1.x);
        B1s[buf][bk][bnv + 1] = tfpack(pB1.y);
        B1s[buf][bk][bnv + 2] = tfpack(pB1.z);
        B1s[buf][bk][bnv + 3] = tfpack(pB1.w);
        B2s[buf][bk][bnv + 0] = tfpack(pB2.x);
        B2s[buf][bk][bnv + 1] = tfpack(pB2.y);
        B2s[buf][bk][bnv + 2] = tfpack(pB2.z);
        B2s[buf][bk][bnv + 3] = tfpack(pB2.w);
    };
    auto compute = [&](int buf) {
#pragma unroll
        for (int ks = 0; ks < 2; ks++) {
            const int k8 = ks * 8;
            uint32_t af[2][4];
#pragma unroll
            for (int im = 0; im < 2; im++) {
                int mr = wm + im * 16 + g;
                af[im][0] = __float_as_uint(As[buf][mr][k8 + tg]);
                af[im][1] = __float_as_uint(As[buf][mr + 8][k8 + tg]);
                af[im][2] = __float_as_uint(As[buf][mr][k8 + tg + 4]);
                af[im][3] = __float_as_uint(As[buf][mr + 8][k8 + tg + 4]);
            }
#pragma unroll
            for (int jn = 0; jn < 4; jn++) {
                int nc = wn + jn * 8 + g;
                uint32_t b10 = __float_as_uint(B1s[buf][k8 + tg][nc]);
                uint32_t b11 = __float_as_uint(B1s[buf][k8 + tg + 4][nc]);
                uint32_t b20 = __float_as_uint(B2s[buf][k8 + tg][nc]);
                uint32_t b21 = __float_as_uint(B2s[buf][k8 + tg + 4][nc]);
#pragma unroll
                for (int im = 0; im < 2; im++) {
                    mma8(c1[im][jn], af[im], b10, b11);
                    mma8(c2[im][jn], af[im], b20, b21);
                }
            }
        }
    };

    const int nkb = DM / 16;  // 64
    ldg_stage(0);
    sts_stage(0);
    __syncthreads();
    for (int kb = 0; kb < nkb; kb++) {
        if (kb + 1 < nkb) ldg_stage(kb + 1);
        compute(kb & 1);
        if (kb + 1 < nkb) sts_stage((kb + 1) & 1);
        __syncthreads();
    }

    // epilogue: h = (A@w1+b1) * silu(A@w2+b2)
#pragma unroll
    for (int im = 0; im < 2; im++) {
#pragma unroll
        for (int jn = 0; jn < 4; jn++) {
            int rlo = row0 + wm + im * 16 + g;
            int nglo = n0 + wn + jn * 8 + 2 * tg;
#pragma unroll
            for (int q = 0; q < 4; q++) {
                int r = rlo + ((q >= 2) ? 8 : 0);
                int nn = nglo + (q & 1);
                if (r < cnt) {
                    float v1 = c1[im][jn][q] + b1[e * DH + nn];
                    float v2 = c2[im][jn][q] + b2[e * DH + nn];
                    float sg = 1.0f / (1.0f + __expf(-v2));
                    g_H[(size_t)(base + r) * DH + nn] = v1 * (v2 * sg);
                }
            }
        }
    }
}

// ---------------- kernel 4: FFN-out  (H @ wo + bo) ---------------------------
__global__ __launch_bounds__(256) void ffn_out_kernel(
    const float* __restrict__ wo, const float* __restrict__ bo)
{
    const int e = blockIdx.z;
    const int cnt = g_cnt[e];
    const int row0 = blockIdx.y * 128;
    if (row0 >= cnt) return;
    const int n0 = blockIdx.x * 64;
    const int base = g_base[e];

    __shared__ float As[2][128][20];
    __shared__ float Bs[2][16][72];

    const int tid = threadIdx.x;
    const int lane = tid & 31;
    const int wid = tid >> 5;
    const int wm = (wid & 3) * 32;
    const int wn = (wid >> 2) * 32;
    const int g = lane >> 2;
    const int tg = lane & 3;

    const float* woe = wo + (size_t)e * DH * DM;

    float c[2][4][4];
#pragma unroll
    for (int i = 0; i < 2; i++)
#pragma unroll
        for (int j = 0; j < 4; j++)
#pragma unroll
            for (int q = 0; q < 4; q++) c[i][j][q] = 0.0f;

    const int amRow0 = tid >> 2;
    const int amRow1 = (tid + 256) >> 2;
    const int akv = (tid & 3) * 4;
    const int bk = tid >> 4;
    const int bnv = (tid & 15) * 4;
    int rA0 = row0 + amRow0; if (rA0 >= cnt) rA0 = cnt - 1;
    int rA1 = row0 + amRow1; if (rA1 >= cnt) rA1 = cnt - 1;
    const size_t aOff0 = (size_t)(base + rA0) * DH + akv;
    const size_t aOff1 = (size_t)(base + rA1) * DH + akv;

    float4 pA0, pA1, pB;

    auto ldg_stage = [&](int kb) {
        pA0 = *(const float4*)(g_H + aOff0 + kb * 16);
        pA1 = *(const float4*)(g_H + aOff1 + kb * 16);
        pB = *(const float4*)(woe + (size_t)(kb * 16 + bk) * DM + n0 + bnv);
    };
    auto sts_stage = [&](int buf) {
        As[buf][amRow0][akv + 0] = tfpack(pA0.x);
        As[buf][amRow0][akv + 1] = tfpack(pA0.y);
        As[buf][amRow0][akv + 2] = tfpack(pA0.z);
        As[buf][amRow0][akv + 3] = tfpack(pA0.w);
        As[buf][amRow1][akv + 0] = tfpack(pA1.x);
        As[buf][amRow1][akv + 1] = tfpack(pA1.y);
        As[buf][amRow1][akv + 2] = tfpack(pA1.z);
        As[buf][amRow1][akv + 3] = tfpack(pA1.w);
        Bs[buf][bk][bnv + 0] = tfpack(pB.x);
        Bs[buf][bk][bnv + 1] = tfpack(pB.y);
        Bs[buf][bk][bnv + 2] = tfpack(pB.z);
        Bs[buf][bk][bnv + 3] = tfpack(pB.w);
    };
    auto compute = [&](int buf) {
#pragma unroll
        for (int ks = 0; ks < 2; ks++) {
            const int k8 = ks * 8;
            uint32_t af[2][4];
#pragma unroll
            for (int im = 0; im < 2; im++) {
                int mr = wm + im * 16 + g;
                af[im][0] = __float_as_uint(As[buf][mr][k8 + tg]);
                af[im][1] = __float_as_uint(As[buf][mr + 8][k8 + tg]);
                af[im][2] = __float_as_uint(As[buf][mr][k8 + tg + 4]);
                af[im][3] = __float_as_uint(As[buf][mr + 8][k8 + tg + 4]);
            }
#pragma unroll
            for (int jn = 0; jn < 4; jn++) {
                int nc = wn + jn * 8 + g;
                uint32_t b0 = __float_as_uint(Bs[buf][k8 + tg][nc]);
                uint32_t b1v = __float_as_uint(Bs[buf][k8 + tg + 4][nc]);
#pragma unroll
                for (int im = 0; im < 2; im++) mma8(c[im][jn], af[im], b0, b1v);
            }
        }
    };

    const int nkb = DH / 16;  // 256
    ldg_stage(0);
    sts_stage(0);
    __syncthreads();
    for (int kb = 0; kb < nkb; kb++) {
        if (kb + 1 < nkb) ldg_stage(kb + 1);
        compute(kb & 1);
        if (kb + 1 < nkb) sts_stage((kb + 1) & 1);
        __syncthreads();
    }

#pragma unroll
    for (int im = 0; im < 2; im++) {
#pragma unroll
        for (int jn = 0; jn < 4; jn++) {
            int rlo = row0 + wm + im * 16 + g;
            int nglo = n0 + wn + jn * 8 + 2 * tg;
#pragma unroll
            for (int q = 0; q < 4; q++) {
                int r = rlo + ((q >= 2) ? 8 : 0);
                int nn = nglo + (q & 1);
                if (r < cnt) {
                    g_Y[(size_t)(base + r) * DM + nn] = c[im][jn][q] + bo[e * DM + nn];
                }
            }
        }
    }
}

// ---------------- kernel 5: deterministic per-token combine ------------------
__global__ void combine_kernel(float* __restrict__ out) {
    int t = blockIdx.x;
    int tid = threadIdx.x;
    int e1 = g_tok_e[2 * t], e2 = g_tok_e[2 * t + 1];
    float w1v = g_tok_w[2 * t], w2v = g_tok_w[2 * t + 1];
    size_t r1 = (size_t)(g_base[e1] + g_tok_slot[2 * t]) * DM;
    size_t r2 = (size_t)(g_base[e2] + g_tok_slot[2 * t + 1]) * DM;
    const float4* y1 = (const float4*)(g_Y + r1);
    const float4* y2 = (const float4*)(g_Y + r2);
    float4 a = y1[tid], b = y2[tid];
    float4 o;
    o.x = w1v * a.x + w2v * b.x;
    o.y = w1v * a.y + w2v * b.y;
    o.z = w1v * a.z + w2v * b.z;
    o.w = w1v * a.w + w2v * b.w;
    ((float4*)(out + (size_t)t * DM))[tid] = o;
}

// ---------------- launch ------------------------------------------------------
extern "C" void kernel_launch(void* const* d_in, const int* in_sizes, int n_in,
                              void* d_out, int out_size) {
    (void)in_sizes; (void)n_in; (void)out_size;
    const float* x  = (const float*)d_in[0];
    const float* rw = (const float*)d_in[1];
    const float* rb = (const float*)d_in[2];
    const float* w1 = (const float*)d_in[3];
    const float* b1 = (const float*)d_in[4];
    const float* w2 = (const float*)d_in[5];
    const float* b2 = (const float*)d_in[6];
    const float* wo = (const float*)d_in[7];
    const float* bo = (const float*)d_in[8];
    float* out = (float*)d_out;

    init_kernel<<<1, 32>>>();
    router_kernel<<<512, 256>>>(x, rw, rb);
    finalize_kernel<<<1, 32>>>(out);
    ffn_in_kernel<<<dim3(DH / 64, T_TOKENS / 128, NE), 256>>>(x, w1, b1, w2, b2);
    ffn_out_kernel<<<dim3(DM / 64, T_TOKENS / 128, NE), 256>>>(wo, bo);
    combine_kernel<<<T_TOKENS, 256>>>(out);
}

// round 2
// speedup vs baseline: 1.0010x; 1.0010x over previous
#include <cuda_runtime.h>
#include <cstdint>

#define T_TOKENS 4096
#define DM 1024
#define DH 4096
#define NE 8

// ---------------- scratch (device globals; no allocations allowed) ----------
__device__ int   g_cnt[NE];
__device__ int   g_base[NE];
__device__ float g_probsum[NE];
__device__ int   g_idx[NE * T_TOKENS];          // token id per (expert, slot)
__device__ int   g_tok_e[T_TOKENS * 2];
__device__ int   g_tok_slot[T_TOKENS * 2];
__device__ float g_tok_w[T_TOKENS * 2];
__device__ float g_H[(size_t)2 * T_TOKENS * DH];  // 8192 x 4096 hidden scratch
__device__ float g_Y[(size_t)2 * T_TOKENS * DM];  // 8192 x 1024 expert-out scratch

// ---------------- helpers ----------------------------------------------------
__device__ __forceinline__ uint32_t f2tf32(float f) {
    uint32_t r;
    asm("cvt.rna.tf32.f32 %0, %1;" : "=r"(r) : "f"(f));
    return r;
}
__device__ __forceinline__ float tfpack(float f) {
    return __uint_as_float(f2tf32(f));
}
__device__ __forceinline__ void mma8(float c[4], const uint32_t a[4],
                                     uint32_t b0, uint32_t b1) {
    asm("mma.sync.aligned.m16n8k8.row.col.f32.tf32.tf32.f32 "
        "{%0,%1,%2,%3}, {%4,%5,%6,%7}, {%8,%9}, {%0,%1,%2,%3};"
        : "+f"(c[0]), "+f"(c[1]), "+f"(c[2]), "+f"(c[3])
        : "r"(a[0]), "r"(a[1]), "r"(a[2]), "r"(a[3]), "r"(b0), "r"(b1));
}

// ---------------- kernel 0: reset counters (graph replays!) ------------------
__global__ void init_kernel() {
    int i = threadIdx.x;
    if (i < NE) { g_cnt[i] = 0; g_probsum[i] = 0.0f; }
}

// ---------------- kernel 1: router (1 warp / token) --------------------------
__global__ __launch_bounds__(256) void router_kernel(
    const float* __restrict__ x, const float* __restrict__ rw,
    const float* __restrict__ rb)
{
    int gwarp = (blockIdx.x * blockDim.x + threadIdx.x) >> 5;
    int lane = threadIdx.x & 31;
    if (gwarp >= T_TOKENS) return;
    const float* xr = x + (size_t)gwarp * DM;

    float acc[NE];
#pragma unroll
    for (int e = 0; e < NE; e++) acc[e] = 0.0f;

    for (int k0 = 0; k0 < DM; k0 += 32) {
        float xv = xr[k0 + lane];
        const float* r = rw + (size_t)(k0 + lane) * NE;
        float4 r0 = *(const float4*)r;
        float4 r1 = *(const float4*)(r + 4);
        acc[0] += xv * r0.x; acc[1] += xv * r0.y;
        acc[2] += xv * r0.z; acc[3] += xv * r0.w;
        acc[4] += xv * r1.x; acc[5] += xv * r1.y;
        acc[6] += xv * r1.z; acc[7] += xv * r1.w;
    }
#pragma unroll
    for (int e = 0; e < NE; e++) {
#pragma unroll
        for (int off = 16; off > 0; off >>= 1)
            acc[e] += __shfl_xor_sync(0xffffffffu, acc[e], off);
    }
    if (lane == 0) {
        float l[NE], p[NE];
        float m = -1e30f;
#pragma unroll
        for (int e = 0; e < NE; e++) { l[e] = acc[e] + rb[e]; m = fmaxf(m, l[e]); }
        float s = 0.0f;
#pragma unroll
        for (int e = 0; e < NE; e++) { p[e] = expf(l[e] - m); s += p[e]; }
        float inv = 1.0f / s;
#pragma unroll
        for (int e = 0; e < NE; e++) {
            p[e] *= inv;
            atomicAdd(&g_probsum[e], p[e]);
        }
        // top-2, ties resolved to earlier index (matches lax.top_k)
        int i1 = 0; float p1 = p[0];
        int i2 = -1; float p2 = -1.0f;
#pragma unroll
        for (int e = 1; e < NE; e++) {
            if (p[e] > p1) { p2 = p1; i2 = i1; p1 = p[e]; i1 = e; }
            else if (p[e] > p2) { p2 = p[e]; i2 = e; }
        }
        int s1 = atomicAdd(&g_cnt[i1], 1);
        g_idx[i1 * T_TOKENS + s1] = gwarp;
        int s2 = atomicAdd(&g_cnt[i2], 1);
        g_idx[i2 * T_TOKENS + s2] = gwarp;
        g_tok_e[2 * gwarp + 0] = i1; g_tok_slot[2 * gwarp + 0] = s1; g_tok_w[2 * gwarp + 0] = p1;
        g_tok_e[2 * gwarp + 1] = i2; g_tok_slot[2 * gwarp + 1] = s2; g_tok_w[2 * gwarp + 1] = p2;
    }
}

// ---------------- kernel 2: scan + lb_loss -----------------------------------
__global__ void finalize_kernel(float* __restrict__ out) {
    if (threadIdx.x == 0 && blockIdx.x == 0) {
        int base = 0;
        float lb = 0.0f;
        for (int e = 0; e < NE; e++) {
            g_base[e] = base;
            base += g_cnt[e];
            float f_i = (float)g_cnt[e] / (float)T_TOKENS;
            float P_i = g_probsum[e] / (float)T_TOKENS;
            lb += f_i * P_i;
        }
        out[(size_t)T_TOKENS * DM] = 0.01f * (float)NE * lb;
    }
}

// ---------------- kernel 3: FFN-in  (gathered, dual-B, SiLU gate) ------------
// Block tile: 128(M rows of one expert) x 64(N of hidden) x K=1024, BK=16.
// 8 warps, each 32x32 warptile -> 2 m16-frags x 4 n8-frags, dual accumulators.
__global__ __launch_bounds__(256) void ffn_in_kernel(
    const float* __restrict__ x,
    const float* __restrict__ w1, const float* __restrict__ b1,
    const float* __restrict__ w2, const float* __restrict__ b2)
{
    const int e = blockIdx.z;
    const int cnt = g_cnt[e];
    const int row0 = blockIdx.y * 128;
    if (row0 >= cnt) return;
    const int n0 = blockIdx.x * 64;
    const int base = g_base[e];

    __shared__ float As[2][128][20];   // [m][k], stride 20 -> conflict-free frags
    __shared__ float B1s[2][16][72];   // [k][n], stride 72
    __shared__ float B2s[2][16][72];
    __shared__ int toks[128];

    const int tid = threadIdx.x;
    if (tid < 128) {
        int r = row0 + tid;
        if (r >= cnt) r = cnt - 1;
        toks[tid] = g_idx[e * T_TOKENS + r];
    }
    __syncthreads();

    const int lane = tid & 31;
    const int wid = tid >> 5;
    const int wm = (wid & 3) * 32;
    const int wn = (wid >> 2) * 32;
    const int g = lane >> 2;
    const int tg = lane & 3;

    const float* w1e = w1 + (size_t)e * DM * DH;
    const float* w2e = w2 + (size_t)e * DM * DH;

    float c1[2][4][4], c2[2][4][4];
#pragma unroll
    for (int i = 0; i < 2; i++)
#pragma unroll
        for (int j = 0; j < 4; j++)
#pragma unroll
            for (int q = 0; q < 4; q++) { c1[i][j][q] = 0.0f; c2[i][j][q] = 0.0f; }

    // staging geometry
    const int amRow0 = tid >> 2;            // 0..63
    const int amRow1 = (tid + 256) >> 2;    // 64..127
    const int akv = (tid & 3) * 4;
    const int bk = tid >> 4;                // 0..15
    const int bnv = (tid & 15) * 4;
    const size_t aOff0 = (size_t)toks[amRow0] * DM + akv;
    const size_t aOff1 = (size_t)toks[amRow1] * DM + akv;

    float4 pA0, pA1, pB1, pB2;

    auto ldg_stage = [&](int kb) {
        pA0 = *(const float4*)(x + aOff0 + kb * 16);
        pA1 = *(const float4*)(x + aOff1 + kb * 16);
        pB1 = *(const float4*)(w1e + (size_t)(kb * 16 + bk) * DH + n0 + bnv);
        pB2 = *(const float4*)(w2e + (size_t)(kb * 16 + bk) * DH + n0 + bnv);
    };
    auto sts_stage = [&](int buf) {
        As[buf][amRow0][akv + 0] = tfpack(pA0.x);
        As[buf][amRow0][akv + 1] = tfpack(pA0.y);
        As[buf][amRow0][akv + 2] = tfpack(pA0.z);
        As[buf][amRow0][akv + 3] = tfpack(pA0.w);
        As[buf][amRow1][akv + 0] = tfpack(pA1.x);
        As[buf][amRow1][akv + 1] = tfpack(pA1.y);
        As[buf][amRow1][akv + 2] = tfpack(pA1.z);
        As[buf][amRow1][akv + 3] = tfpack(pA1.w);
        B1s[buf][bk][bnv + 0] = tfpack(pB1.x);
        B1s[buf][bk][bnv + 1] = tfpack(pB1.y);
        B1s[buf][bk][bnv + 2] = tfpack(pB1.z);
        B1s[buf][bk][bnv + 3] = tfpack(pB1.w);
        B2s[buf][bk][bnv + 0] = tfpack(pB2.x);
        B2s[buf][bk][bnv + 1] = tfpack(pB2.y);
        B2s[buf][bk][bnv + 2] = tfpack(pB2.z);
        B2s[buf][bk][bnv + 3] = tfpack(pB2.w);
    };
    auto compute = [&](int buf) {
#pragma unroll
        for (int ks = 0; ks < 2; ks++) {
            const int k8 = ks * 8;
            uint32_t af[2][4];
#pragma unroll
            for (int im = 0; im < 2; im++) {
                int mr = wm + im * 16 + g;
                af[im][0] = __float_as_uint(As[buf][mr][k8 + tg]);
                af[im][1] = __float_as_uint(As[buf][mr + 8][k8 + tg]);
                af[im][2] = __float_as_uint(As[buf][mr][k8 + tg + 4]);
                af[im][3] = __float_as_uint(As[buf][mr + 8][k8 + tg + 4]);
            }
#pragma unroll
            for (int jn = 0; jn < 4; jn++) {
                int nc = wn + jn * 8 + g;
                uint32_t b10 = __float_as_uint(B1s[buf][k8 + tg][nc]);
                uint32_t b11 = __float_as_uint(B1s[buf][k8 + tg + 4][nc]);
                uint32_t b20 = __float_as_uint(B2s[buf][k8 + tg][nc]);
                uint32_t b21 = __float_as_uint(B2s[buf][k8 + tg + 4][nc]);
#pragma unroll
                for (int im = 0; im < 2; im++) {
                    mma8(c1[im][jn], af[im], b10, b11);
                    mma8(c2[im][jn], af[im], b20, b21);
                }
            }
        }
    };

    const int nkb = DM / 16;  // 64
    ldg_stage(0);
    sts_stage(0);
    __syncthreads();
    for (int kb = 0; kb < nkb; kb++) {
        if (kb + 1 < nkb) ldg_stage(kb + 1);
        compute(kb & 1);
        if (kb + 1 < nkb) sts_stage((kb + 1) & 1);
        __syncthreads();
    }

    // epilogue: h = (A@w1+b1) * silu(A@w2+b2)
#pragma unroll
    for (int im = 0; im < 2; im++) {
#pragma unroll
        for (int jn = 0; jn < 4; jn++) {
            int rlo = row0 + wm + im * 16 + g;
            int nglo = n0 + wn + jn * 8 + 2 * tg;
#pragma unroll
            for (int q = 0; q < 4; q++) {
                int r = rlo + ((q >= 2) ? 8 : 0);
                int nn = nglo + (q & 1);
                if (r < cnt) {
                    float v1 = c1[im][jn][q] + b1[e * DH + nn];
                    float v2 = c2[im][jn][q] + b2[e * DH + nn];
                    float sg = 1.0f / (1.0f + __expf(-v2));
                    g_H[(size_t)(base + r) * DH + nn] = v1 * (v2 * sg);
                }
            }
        }
    }
}

// ---------------- kernel 4: FFN-out  (H @ wo + bo) ---------------------------
__global__ __launch_bounds__(256) void ffn_out_kernel(
    const float* __restrict__ wo, const float* __restrict__ bo)
{
    const int e = blockIdx.z;
    const int cnt = g_cnt[e];
    const int row0 = blockIdx.y * 128;
    if (row0 >= cnt) return;
    const int n0 = blockIdx.x * 64;
    const int base = g_base[e];

    __shared__ float As[2][128][20];
    __shared__ float Bs[2][16][72];

    const int tid = threadIdx.x;
    const int lane = tid & 31;
    const int wid = tid >> 5;
    const int wm = (wid & 3) * 32;
    const int wn = (wid >> 2) * 32;
    const int g = lane >> 2;
    const int tg = lane & 3;

    const float* woe = wo + (size_t)e * DH * DM;

    float c[2][4][4];
#pragma unroll
    for (int i = 0; i < 2; i++)
#pragma unroll
        for (int j = 0; j < 4; j++)
#pragma unroll
            for (int q = 0; q < 4; q++) c[i][j][q] = 0.0f;

    const int amRow0 = tid >> 2;
    const int amRow1 = (tid + 256) >> 2;
    const int akv = (tid & 3) * 4;
    const int bk = tid >> 4;
    const int bnv = (tid & 15) * 4;
    int rA0 = row0 + amRow0; if (rA0 >= cnt) rA0 = cnt - 1;
    int rA1 = row0 + amRow1; if (rA1 >= cnt) rA1 = cnt - 1;
    const size_t aOff0 = (size_t)(base + rA0) * DH + akv;
    const size_t aOff1 = (size_t)(base + rA1) * DH + akv;

    float4 pA0, pA1, pB;

    auto ldg_stage = [&](int kb) {
        pA0 = *(const float4*)(g_H + aOff0 + kb * 16);
        pA1 = *(const float4*)(g_H + aOff1 + kb * 16);
        pB = *(const float4*)(woe + (size_t)(kb * 16 + bk) * DM + n0 + bnv);
    };
    auto sts_stage = [&](int buf) {
        As[buf][amRow0][akv + 0] = tfpack(pA0.x);
        As[buf][amRow0][akv + 1] = tfpack(pA0.y);
        As[buf][amRow0][akv + 2] = tfpack(pA0.z);
        As[buf][amRow0][akv + 3] = tfpack(pA0.w);
        As[buf][amRow1][akv + 0] = tfpack(pA1.x);
        As[buf][amRow1][akv + 1] = tfpack(pA1.y);
        As[buf][amRow1][akv + 2] = tfpack(pA1.z);
        As[buf][amRow1][akv + 3] = tfpack(pA1.w);
        Bs[buf][bk][bnv + 0] = tfpack(pB.x);
        Bs[buf][bk][bnv + 1] = tfpack(pB.y);
        Bs[buf][bk][bnv + 2] = tfpack(pB.z);
        Bs[buf][bk][bnv + 3] = tfpack(pB.w);
    };
    auto compute = [&](int buf) {
#pragma unroll
        for (int ks = 0; ks < 2; ks++) {
            const int k8 = ks * 8;
            uint32_t af[2][4];
#pragma unroll
            for (int im = 0; im < 2; im++) {
                int mr = wm + im * 16 + g;
                af[im][0] = __float_as_uint(As[buf][mr][k8 + tg]);
                af[im][1] = __float_as_uint(As[buf][mr + 8][k8 + tg]);
                af[im][2] = __float_as_uint(As[buf][mr][k8 + tg + 4]);
                af[im][3] = __float_as_uint(As[buf][mr + 8][k8 + tg + 4]);
            }
#pragma unroll
            for (int jn = 0; jn < 4; jn++) {
                int nc = wn + jn * 8 + g;
                uint32_t b0 = __float_as_uint(Bs[buf][k8 + tg][nc]);
                uint32_t b1v = __float_as_uint(Bs[buf][k8 + tg + 4][nc]);
#pragma unroll
                for (int im = 0; im < 2; im++) mma8(c[im][jn], af[im], b0, b1v);
            }
        }
    };

    const int nkb = DH / 16;  // 256
    ldg_stage(0);
    sts_stage(0);
    __syncthreads();
    for (int kb = 0; kb < nkb; kb++) {
        if (kb + 1 < nkb) ldg_stage(kb + 1);
        compute(kb & 1);
        if (kb + 1 < nkb) sts_stage((kb + 1) & 1);
        __syncthreads();
    }

#pragma unroll
    for (int im = 0; im < 2; im++) {
#pragma unroll
        for (int jn = 0; jn < 4; jn++) {
            int rlo = row0 + wm + im * 16 + g;
            int nglo = n0 + wn + jn * 8 + 2 * tg;
#pragma unroll
            for (int q = 0; q < 4; q++) {
                int r = rlo + ((q >= 2) ? 8 : 0);
                int nn = nglo + (q & 1);
                if (r < cnt) {
                    g_Y[(size_t)(base + r) * DM + nn] = c[im][jn][q] + bo[e * DM + nn];
                }
            }
        }
    }
}

// ---------------- kernel 5: deterministic per-token combine ------------------
__global__ void combine_kernel(float* __restrict__ out) {
    int t = blockIdx.x;
    int tid = threadIdx.x;
    int e1 = g_tok_e[2 * t], e2 = g_tok_e[2 * t + 1];
    float w1v = g_tok_w[2 * t], w2v = g_tok_w[2 * t + 1];
    size_t r1 = (size_t)(g_base[e1] + g_tok_slot[2 * t]) * DM;
    size_t r2 = (size_t)(g_base[e2] + g_tok_slot[2 * t + 1]) * DM;
    const float4* y1 = (const float4*)(g_Y + r1);
    const float4* y2 = (const float4*)(g_Y + r2);
    float4 a = y1[tid], b = y2[tid];
    float4 o;
    o.x = w1v * a.x + w2v * b.x;
    o.y = w1v * a.y + w2v * b.y;
    o.z = w1v * a.z + w2v * b.z;
    o.w = w1v * a.w + w2v * b.w;
    ((float4*)(out + (size_t)t * DM))[tid] = o;
}

// ---------------- launch ------------------------------------------------------
extern "C" void kernel_launch(void* const* d_in, const int* in_sizes, int n_in,
                              void* d_out, int out_size) {
    (void)in_sizes; (void)n_in; (void)out_size;
    const float* x  = (const float*)d_in[0];
    const float* rw = (const float*)d_in[1];
    const float* rb = (const float*)d_in[2];
    const float* w1 = (const float*)d_in[3];
    const float* b1 = (const float*)d_in[4];
    const float* w2 = (const float*)d_in[5];
    const float* b2 = (const float*)d_in[6];
    const float* wo = (const float*)d_in[7];
    const float* bo = (const float*)d_in[8];
    float* out = (float*)d_out;

    init_kernel<<<1, 32>>>();
    router_kernel<<<512, 256>>>(x, rw, rb);
    finalize_kernel<<<1, 32>>>(out);
    ffn_in_kernel<<<dim3(DH / 64, T_TOKENS / 128, NE), 256>>>(x, w1, b1, w2, b2);
    ffn_out_kernel<<<dim3(DM / 64, T_TOKENS / 128, NE), 256>>>(wo, bo);
    combine_kernel<<<T_TOKENS, 256>>>(out);
}

// round 4
// speedup vs baseline: 1.7126x; 1.7108x over previous
#include <cuda_runtime.h>
#include <cuda_fp16.h>
#include <cstdint>

#define T_TOKENS 4096
#define DM 1024
#define DH 4096
#define NE 8

// ---------------- scratch (device globals) -----------------------------------
__device__ int   g_cnt[NE];
__device__ int   g_base[NE];
__device__ float g_probsum[NE];
__device__ int   g_idx[NE * T_TOKENS];
__device__ int   g_tok_e[T_TOKENS * 2];
__device__ int   g_tok_slot[T_TOKENS * 2];
__device__ float g_tok_w[T_TOKENS * 2];
__device__ __half g_xh[(size_t)T_TOKENS * DM];          // 8 MB
__device__ __half g_Hh[(size_t)2 * T_TOKENS * DH];      // 64 MB
__device__ float  g_Y[(size_t)2 * T_TOKENS * DM];       // 64 MB
__device__ uint4  g_w12t[(size_t)NE * 32 * 64 * 512];   // w1+w2 frag-tiled fp16, 128 MB
__device__ uint2  g_wot[(size_t)NE * 8 * 256 * 512];    // wo frag-tiled fp16, 64 MB

// ---------------- helpers -----------------------------------------------------
__device__ __forceinline__ uint32_t smem_u32(const void* p) {
    uint32_t a;
    asm("{ .reg .u64 t; cvta.to.shared.u64 t, %1; cvt.u32.u64 %0, t; }" : "=r"(a) : "l"(p));
    return a;
}
__device__ __forceinline__ uint32_t pk(float lo, float hi) {
    __half2 h = __floats2half2_rn(lo, hi);
    return *(uint32_t*)&h;
}
__device__ __forceinline__ void cp16(uint32_t dst, const void* src) {
    asm volatile("cp.async.cg.shared.global [%0], [%1], 16;" :: "r"(dst), "l"(src) : "memory");
}
__device__ __forceinline__ void cp_commit() {
    asm volatile("cp.async.commit_group;" ::: "memory");
}
__device__ __forceinline__ void cp_wait3() {
    asm volatile("cp.async.wait_group 3;" ::: "memory");
}
__device__ __forceinline__ void ldm4(uint32_t a[4], uint32_t addr) {
    asm volatile("ldmatrix.sync.aligned.m8n8.x4.shared.b16 {%0,%1,%2,%3}, [%4];"
                 : "=r"(a[0]), "=r"(a[1]), "=r"(a[2]), "=r"(a[3]) : "r"(addr));
}
__device__ __forceinline__ void mma16(float c[4], const uint32_t a[4],
                                      uint32_t b0, uint32_t b1) {
    asm volatile("mma.sync.aligned.m16n8k16.row.col.f32.f16.f16.f32 "
                 "{%0,%1,%2,%3}, {%4,%5,%6,%7}, {%8,%9}, {%0,%1,%2,%3};"
                 : "+f"(c[0]), "+f"(c[1]), "+f"(c[2]), "+f"(c[3])
                 : "r"(a[0]), "r"(a[1]), "r"(a[2]), "r"(a[3]), "r"(b0), "r"(b1));
}

// ---------------- kernel 0: reset ---------------------------------------------
__global__ void init_kernel() {
    int i = threadIdx.x;
    if (i < NE) { g_cnt[i] = 0; g_probsum[i] = 0.0f; }
}

// ---------------- kernel 1: router --------------------------------------------
__global__ __launch_bounds__(256) void router_kernel(
    const float* __restrict__ x, const float* __restrict__ rw, const float* __restrict__ rb)
{
    int gwarp = (blockIdx.x * blockDim.x + threadIdx.x) >> 5;
    int lane = threadIdx.x & 31;
    if (gwarp >= T_TOKENS) return;
    const float* xr = x + (size_t)gwarp * DM;
    float acc[NE];
#pragma unroll
    for (int e = 0; e < NE; e++) acc[e] = 0.0f;
    for (int k0 = 0; k0 < DM; k0 += 32) {
        float xv = xr[k0 + lane];
        const float* r = rw + (size_t)(k0 + lane) * NE;
        float4 r0 = *(const float4*)r;
        float4 r1 = *(const float4*)(r + 4);
        acc[0] += xv * r0.x; acc[1] += xv * r0.y;
        acc[2] += xv * r0.z; acc[3] += xv * r0.w;
        acc[4] += xv * r1.x; acc[5] += xv * r1.y;
        acc[6] += xv * r1.z; acc[7] += xv * r1.w;
    }
#pragma unroll
    for (int e = 0; e < NE; e++)
#pragma unroll
        for (int off = 16; off > 0; off >>= 1)
            acc[e] += __shfl_xor_sync(0xffffffffu, acc[e], off);
    if (lane == 0) {
        float l[NE], p[NE];
        float m = -1e30f;
#pragma unroll
        for (int e = 0; e < NE; e++) { l[e] = acc[e] + rb[e]; m = fmaxf(m, l[e]); }
        float s = 0.0f;
#pragma unroll
        for (int e = 0; e < NE; e++) { p[e] = expf(l[e] - m); s += p[e]; }
        float inv = 1.0f / s;
#pragma unroll
        for (int e = 0; e < NE; e++) { p[e] *= inv; atomicAdd(&g_probsum[e], p[e]); }
        int i1 = 0; float p1 = p[0];
        int i2 = -1; float p2 = -1.0f;
#pragma unroll
        for (int e = 1; e < NE; e++) {
            if (p[e] > p1) { p2 = p1; i2 = i1; p1 = p[e]; i1 = e; }
            else if (p[e] > p2) { p2 = p[e]; i2 = e; }
        }
        int s1 = atomicAdd(&g_cnt[i1], 1);
        g_idx[i1 * T_TOKENS + s1] = gwarp;
        int s2 = atomicAdd(&g_cnt[i2], 1);
        g_idx[i2 * T_TOKENS + s2] = gwarp;
        g_tok_e[2 * gwarp + 0] = i1; g_tok_slot[2 * gwarp + 0] = s1; g_tok_w[2 * gwarp + 0] = p1;
        g_tok_e[2 * gwarp + 1] = i2; g_tok_slot[2 * gwarp + 1] = s2; g_tok_w[2 * gwarp + 1] = p2;
    }
}

// ---------------- kernel 2: scan + lb_loss ------------------------------------
__global__ void finalize_kernel(float* __restrict__ out) {
    if (threadIdx.x == 0 && blockIdx.x == 0) {
        int base = 0;
        float lb = 0.0f;
        for (int e = 0; e < NE; e++) {
            g_base[e] = base;
            base += g_cnt[e];
            lb += ((float)g_cnt[e] / T_TOKENS) * (g_probsum[e] / T_TOKENS);
        }
        out[(size_t)T_TOKENS * DM] = 0.01f * (float)NE * lb;
    }
}

// ---------------- prep kernels -------------------------------------------------
__global__ __launch_bounds__(256) void prep_x(const float* __restrict__ x) {
    size_t i = ((size_t)blockIdx.x * 256 + threadIdx.x) * 4;
    float4 v = *(const float4*)(x + i);
    uint2 o;
    o.x = pk(v.x, v.y);
    o.y = pk(v.z, v.w);
    *(uint2*)(g_xh + i) = o;
}

// w1,w2 [E][DM][DH] -> frag tiles [e][nblk(32 of 128n)][kb(64 of 16k)][slot 512] x uint4
__global__ __launch_bounds__(256) void prep_w12(
    const float* __restrict__ w1, const float* __restrict__ w2)
{
    const int kb = blockIdx.x, nblk = blockIdx.y, e = blockIdx.z;
    __shared__ float s1[16][132], s2[16][132];
    const float* w1e = w1 + (size_t)e * DM * DH + (size_t)(kb * 16) * DH + nblk * 128;
    const float* w2e = w2 + (size_t)e * DM * DH + (size_t)(kb * 16) * DH + nblk * 128;
    const int tid = threadIdx.x;
#pragma unroll
    for (int r = 0; r < 2; r++) {
        int t2 = tid + r * 256;
        int k = t2 >> 5, n4 = (t2 & 31) * 4;
        float4 v = *(const float4*)(w1e + (size_t)k * DH + n4);
        s1[k][n4] = v.x; s1[k][n4 + 1] = v.y; s1[k][n4 + 2] = v.z; s1[k][n4 + 3] = v.w;
        v = *(const float4*)(w2e + (size_t)k * DH + n4);
        s2[k][n4] = v.x; s2[k][n4 + 1] = v.y; s2[k][n4 + 2] = v.z; s2[k][n4 + 3] = v.w;
    }
    __syncthreads();
    uint4* dst = g_w12t + ((size_t)((e * 32 + nblk) * 64 + kb)) * 512;
#pragma unroll
    for (int r = 0; r < 2; r++) {
        int slot = tid + r * 256;
        int lane = slot & 31, jn8 = slot >> 5;
        int col = jn8 * 8 + (lane >> 2);
        int k2 = (lane & 3) * 2;
        uint4 o;
        o.x = pk(s1[k2][col], s1[k2 + 1][col]);
        o.y = pk(s1[k2 + 8][col], s1[k2 + 9][col]);
        o.z = pk(s2[k2][col], s2[k2 + 1][col]);
        o.w = pk(s2[k2 + 8][col], s2[k2 + 9][col]);
        dst[slot] = o;
    }
}

// wo [E][DH][DM] -> frag tiles [e][nblk(8 of 128n)][kb(256 of 16k)][slot 512] x uint2
__global__ __launch_bounds__(256) void prep_wo(const float* __restrict__ wo) {
    const int kb = blockIdx.x, nblk = blockIdx.y, e = blockIdx.z;
    __shared__ float s[16][132];
    const float* we = wo + (size_t)e * DH * DM + (size_t)(kb * 16) * DM + nblk * 128;
    const int tid = threadIdx.x;
#pragma unroll
    for (int r = 0; r < 2; r++) {
        int t2 = tid + r * 256;
        int k = t2 >> 5, n4 = (t2 & 31) * 4;
        float4 v = *(const float4*)(we + (size_t)k * DM + n4);
        s[k][n4] = v.x; s[k][n4 + 1] = v.y; s[k][n4 + 2] = v.z; s[k][n4 + 3] = v.w;
    }
    __syncthreads();
    uint2* dst = g_wot + ((size_t)((e * 8 + nblk) * 256 + kb)) * 512;
#pragma unroll
    for (int r = 0; r < 2; r++) {
        int slot = tid + r * 256;
        int lane = slot & 31, jn8 = slot >> 5;
        int col = jn8 * 8 + (lane >> 2);
        int k2 = (lane & 3) * 2;
        uint2 o;
        o.x = pk(s[k2][col], s[k2 + 1][col]);
        o.y = pk(s[k2 + 8][col], s[k2 + 9][col]);
        dst[slot] = o;
    }
}

// ---------------- kernel 3: FFN-in (fp16 mma, dual-B, SiLU gate) ---------------
// 512 thr, tile 128m x 128n x K=1024, 16 warps of 32x32 (dual accumulators)
#define FI_STAGE 14336
#define FI_B 6144
#define FI_TOK (4 * FI_STAGE)
#define FI_BB1 (FI_TOK + 512)
#define FI_BB2 (FI_BB1 + 512)
#define FI_SMEM (FI_BB2 + 512)

__global__ __launch_bounds__(512, 1) void ffn_in_h(
    const float* __restrict__ b1, const float* __restrict__ b2)
{
    const int e = blockIdx.z, nblk = blockIdx.y;
    const int cnt = g_cnt[e];
    const int row0 = blockIdx.x * 128;
    if (row0 >= cnt) return;
    const int n0 = nblk * 128;
    const int base = g_base[e];

    extern __shared__ __align__(16) char smem[];
    const uint32_t sb = smem_u32(smem);
    const int tid = threadIdx.x;
    const int lane = tid & 31, wid = tid >> 5;
    const int wm = (wid & 3) * 32, wn = (wid >> 2) * 32;
    const int g = lane >> 2, tg = lane & 3;

    int* toks = (int*)(smem + FI_TOK);
    float* bb1 = (float*)(smem + FI_BB1);
    float* bb2 = (float*)(smem + FI_BB2);
    if (tid < 128) {
        int r = row0 + tid;
        if (r >= cnt) r = cnt - 1;
        toks[tid] = g_idx[e * T_TOKENS + r];
    } else if (tid < 256) bb1[tid - 128] = b1[e * DH + n0 + (tid - 128)];
    else if (tid < 384)   bb2[tid - 256] = b2[e * DH + n0 + (tid - 256)];
    __syncthreads();

    const char* asrc = nullptr;
    uint32_t adst = 0;
    if (tid < 256) {
        int arow = tid >> 1, ac = tid & 1;
        asrc = (const char*)(g_xh + (size_t)toks[arow] * DM) + ac * 16;
        adst = sb + arow * 48 + ac * 16;
    }
    const char* bsrc = (const char*)(g_w12t + ((size_t)(e * 32 + nblk) * 64) * 512 + tid);
    const uint32_t bdst = sb + FI_B + tid * 16;

    float c1[2][4][4], c2[2][4][4];
#pragma unroll
    for (int i = 0; i < 2; i++)
#pragma unroll
        for (int j = 0; j < 4; j++)
#pragma unroll
            for (int q = 0; q < 4; q++) { c1[i][j][q] = 0.0f; c2[i][j][q] = 0.0f; }

    auto stage = [&](int kt, int buf) {
        uint32_t o = buf * FI_STAGE;
        if (tid < 256) cp16(adst + o, asrc + (size_t)kt * 32);
        cp16(bdst + o, bsrc + (size_t)kt * 8192);
    };

    stage(0, 0); cp_commit();
    stage(1, 1); cp_commit();
    stage(2, 2); cp_commit();

    const uint32_t lrow = lane & 15, lhalf = lane >> 4;
    for (int kt = 0; kt < 64; kt++) {
        if (kt + 3 < 64) stage(kt + 3, (kt + 3) & 3);
        cp_commit();
        cp_wait3();
        __syncthreads();
        const uint32_t so = (kt & 3) * FI_STAGE;
        uint32_t a[2][4];
#pragma unroll
        for (int im = 0; im < 2; im++)
            ldm4(a[im], sb + so + (wm + im * 16 + lrow) * 48 + lhalf * 16);
#pragma unroll
        for (int jn = 0; jn < 4; jn++) {
            const char* bp = smem + so + FI_B + ((((wn >> 3) + jn) * 32 + lane) << 4);
            uint2 v1 = *(const uint2*)bp;
            uint2 v2 = *(const uint2*)(bp + 8);
            mma16(c1[0][jn], a[0], v1.x, v1.y);
            mma16(c1[1][jn], a[1], v1.x, v1.y);
            mma16(c2[0][jn], a[0], v2.x, v2.y);
            mma16(c2[1][jn], a[1], v2.x, v2.y);
        }
        __syncthreads();
    }

    // epilogue: h = (d1+b1) * silu(d2+b2) -> g_Hh (fp16)
#pragma unroll
    for (int im = 0; im < 2; im++) {
#pragma unroll
        for (int jn = 0; jn < 4; jn++) {
            int colL = wn + jn * 8 + 2 * tg;
            float bv1a = bb1[colL], bv1b = bb1[colL + 1];
            float bv2a = bb2[colL], bv2b = bb2[colL + 1];
            int r0 = row0 + wm + im * 16 + g;
            size_t colG = (size_t)n0 + colL;
            if (r0 < cnt) {
                float v1 = c1[im][jn][0] + bv1a, w = c2[im][jn][0] + bv2a;
                float h0 = v1 * w / (1.0f + __expf(-w));
                v1 = c1[im][jn][1] + bv1b; w = c2[im][jn][1] + bv2b;
                float h1 = v1 * w / (1.0f + __expf(-w));
                *(uint32_t*)(g_Hh + (size_t)(base + r0) * DH + colG) = pk(h0, h1);
            }
            int r1 = r0 + 8;
            if (r1 < cnt) {
                float v1 = c1[im][jn][2] + bv1a, w = c2[im][jn][2] + bv2a;
                float h0 = v1 * w / (1.0f + __expf(-w));
                v1 = c1[im][jn][3] + bv1b; w = c2[im][jn][3] + bv2b;
                float h1 = v1 * w / (1.0f + __expf(-w));
                *(uint32_t*)(g_Hh + (size_t)(base + r1) * DH + colG) = pk(h0, h1);
            }
        }
    }
}

// ---------------- kernel 4: FFN-out (fp16 mma) ---------------------------------
#define FO_STAGE 10240
#define FO_B 6144
#define FO_BB (4 * FO_STAGE)
#define FO_SMEM (FO_BB + 512)

__global__ __launch_bounds__(512, 1) void ffn_out_h(const float* __restrict__ bo) {
    const int e = blockIdx.z, nblk = blockIdx.y;
    const int cnt = g_cnt[e];
    const int row0 = blockIdx.x * 128;
    if (row0 >= cnt) return;
    const int n0 = nblk * 128;
    const int base = g_base[e];

    __shared__ __align__(16) char smem[FO_SMEM];
    const uint32_t sb = smem_u32(smem);
    const int tid = threadIdx.x;
    const int lane = tid & 31, wid = tid >> 5;
    const int wm = (wid & 3) * 32, wn = (wid >> 2) * 32;
    const int g = lane >> 2, tg = lane & 3;

    float* bb = (float*)(smem + FO_BB);
    if (tid < 128) bb[tid] = bo[e * DM + n0 + tid];
    __syncthreads();

    const char* asrc = nullptr;
    uint32_t adst = 0;
    const char* bsrc = nullptr;
    uint32_t bdst = 0;
    if (tid < 256) {
        int arow = tid >> 1, ac = tid & 1;
        int r = row0 + arow;
        if (r >= cnt) r = cnt - 1;
        asrc = (const char*)(g_Hh + (size_t)(base + r) * DH) + ac * 16;
        adst = sb + arow * 48 + ac * 16;
    } else {
        int slot = tid - 256;
        bsrc = (const char*)((const uint4*)g_wot + ((size_t)(e * 8 + nblk) * 256) * 256 + slot);
        bdst = sb + FO_B + slot * 16;
    }

    float c[2][4][4];
#pragma unroll
    for (int i = 0; i < 2; i++)
#pragma unroll
        for (int j = 0; j < 4; j++)
#pragma unroll
            for (int q = 0; q < 4; q++) c[i][j][q] = 0.0f;

    auto stage = [&](int kt, int buf) {
        uint32_t o = buf * FO_STAGE;
        if (tid < 256) cp16(adst + o, asrc + (size_t)kt * 32);
        else           cp16(bdst + o, bsrc + (size_t)kt * 4096);
    };

    stage(0, 0); cp_commit();
    stage(1, 1); cp_commit();
    stage(2, 2); cp_commit();

    const uint32_t lrow = lane & 15, lhalf = lane >> 4;
    for (int kt = 0; kt < 256; kt++) {
        if (kt + 3 < 256) stage(kt + 3, (kt + 3) & 3);
        cp_commit();
        cp_wait3();
        __syncthreads();
        const uint32_t so = (kt & 3) * FO_STAGE;
        uint32_t a[2][4];
#pragma unroll
        for (int im = 0; im < 2; im++)
            ldm4(a[im], sb + so + (wm + im * 16 + lrow) * 48 + lhalf * 16);
#pragma unroll
        for (int jn = 0; jn < 4; jn++) {
            const char* bp = smem + so + FO_B + ((((wn >> 3) + jn) * 32 + lane) << 3);
            uint2 v = *(const uint2*)bp;
            mma16(c[0][jn], a[0], v.x, v.y);
            mma16(c[1][jn], a[1], v.x, v.y);
        }
        __syncthreads();
    }

#pragma unroll
    for (int im = 0; im < 2; im++) {
#pragma unroll
        for (int jn = 0; jn < 4; jn++) {
            int colL = wn + jn * 8 + 2 * tg;
            float ba = bb[colL], bbv = bb[colL + 1];
            int r0 = row0 + wm + im * 16 + g;
            size_t colG = (size_t)n0 + colL;
            if (r0 < cnt) {
                float2 o;
                o.x = c[im][jn][0] + ba;
                o.y = c[im][jn][1] + bbv;
                *(float2*)(g_Y + (size_t)(base + r0) * DM + colG) = o;
            }
            int r1 = r0 + 8;
            if (r1 < cnt) {
                float2 o;
                o.x = c[im][jn][2] + ba;
                o.y = c[im][jn][3] + bbv;
                *(float2*)(g_Y + (size_t)(base + r1) * DM + colG) = o;
            }
        }
    }
}

// ---------------- kernel 5: combine --------------------------------------------
__global__ void combine_kernel(float* __restrict__ out) {
    int t = blockIdx.x;
    int tid = threadIdx.x;
    int e1 = g_tok_e[2 * t], e2 = g_tok_e[2 * t + 1];
    float w1v = g_tok_w[2 * t], w2v = g_tok_w[2 * t + 1];
    size_t r1 = (size_t)(g_base[e1] + g_tok_slot[2 * t]) * DM;
    size_t r2 = (size_t)(g_base[e2] + g_tok_slot[2 * t + 1]) * DM;
    float4 a = ((const float4*)(g_Y + r1))[tid];
    float4 b = ((const float4*)(g_Y + r2))[tid];
    float4 o;
    o.x = w1v * a.x + w2v * b.x;
    o.y = w1v * a.y + w2v * b.y;
    o.z = w1v * a.z + w2v * b.z;
    o.w = w1v * a.w + w2v * b.w;
    ((float4*)(out + (size_t)t * DM))[tid] = o;
}

// ---------------- launch -------------------------------------------------------
extern "C" void kernel_launch(void* const* d_in, const int* in_sizes, int n_in,
                              void* d_out, int out_size) {
    (void)in_sizes; (void)n_in; (void)out_size;
    const float* x  = (const float*)d_in[0];
    const float* rw = (const float*)d_in[1];
    const float* rb = (const float*)d_in[2];
    const float* w1 = (const float*)d_in[3];
    const float* b1 = (const float*)d_in[4];
    const float* w2 = (const float*)d_in[5];
    const float* b2 = (const float*)d_in[6];
    const float* wo = (const float*)d_in[7];
    const float* bo = (const float*)d_in[8];
    float* out = (float*)d_out;

    cudaFuncSetAttribute(ffn_in_h, cudaFuncAttributeMaxDynamicSharedMemorySize, FI_SMEM);

    init_kernel<<<1, 32>>>();
    router_kernel<<<512, 256>>>(x, rw, rb);
    finalize_kernel<<<1, 32>>>(out);
    prep_x<<<(T_TOKENS * DM) / 1024, 256>>>(x);
    prep_w12<<<dim3(64, 32, NE), 256>>>(w1, w2);
    prep_wo<<<dim3(256, 8, NE), 256>>>(wo);
    ffn_in_h<<<dim3(T_TOKENS / 128, DH / 128, NE), 512, FI_SMEM>>>(b1, b2);
    ffn_out_h<<<dim3(T_TOKENS / 128, DM / 128, NE), 512>>>(bo);
    combine_kernel<<<T_TOKENS, 256>>>(out);
}

// round 5
// speedup vs baseline: 1.8813x; 1.0985x over previous
#include <cuda_runtime.h>
#include <cuda_fp16.h>
#include <cstdint>

#define T_TOKENS 4096
#define DM 1024
#define DH 4096
#define NE 8

// ---------------- scratch (device globals) -----------------------------------
__device__ int   g_cnt[NE];
__device__ int   g_base[NE];
__device__ float g_probsum[NE];
__device__ int   g_idx[NE * T_TOKENS];
__device__ int   g_tok_e[T_TOKENS * 2];
__device__ int   g_tok_slot[T_TOKENS * 2];
__device__ float g_tok_w[T_TOKENS * 2];
__device__ __half g_xh[(size_t)T_TOKENS * DM];
__device__ __half g_Hh[(size_t)2 * T_TOKENS * DH];
__device__ float  g_Y[(size_t)2 * T_TOKENS * DM];
__device__ uint4  g_w12t[(size_t)NE * 32 * 64 * 512];
__device__ uint2  g_wot[(size_t)NE * 8 * 256 * 512];

// ---------------- helpers -----------------------------------------------------
__device__ __forceinline__ uint32_t smem_u32(const void* p) {
    uint32_t a;
    asm("{ .reg .u64 t; cvta.to.shared.u64 t, %1; cvt.u32.u64 %0, t; }" : "=r"(a) : "l"(p));
    return a;
}
__device__ __forceinline__ uint32_t pk(float lo, float hi) {
    __half2 h = __floats2half2_rn(lo, hi);
    return *(uint32_t*)&h;
}
__device__ __forceinline__ void cp16(uint32_t dst, const void* src) {
    asm volatile("cp.async.cg.shared.global [%0], [%1], 16;" :: "r"(dst), "l"(src) : "memory");
}
__device__ __forceinline__ void cp_commit() {
    asm volatile("cp.async.commit_group;" ::: "memory");
}
__device__ __forceinline__ void cp_wait3() {
    asm volatile("cp.async.wait_group 3;" ::: "memory");
}
__device__ __forceinline__ void ldm4(uint32_t a[4], uint32_t addr) {
    asm volatile("ldmatrix.sync.aligned.m8n8.x4.shared.b16 {%0,%1,%2,%3}, [%4];"
                 : "=r"(a[0]), "=r"(a[1]), "=r"(a[2]), "=r"(a[3]) : "r"(addr));
}
__device__ __forceinline__ void mma16(float c[4], const uint32_t a[4],
                                      uint32_t b0, uint32_t b1) {
    asm volatile("mma.sync.aligned.m16n8k16.row.col.f32.f16.f16.f32 "
                 "{%0,%1,%2,%3}, {%4,%5,%6,%7}, {%8,%9}, {%0,%1,%2,%3};"
                 : "+f"(c[0]), "+f"(c[1]), "+f"(c[2]), "+f"(c[3])
                 : "r"(a[0]), "r"(a[1]), "r"(a[2]), "r"(a[3]), "r"(b0), "r"(b1));
}

// ---------------- kernel 0: reset ---------------------------------------------
__global__ void init_kernel() {
    int i = threadIdx.x;
    if (i < NE) { g_cnt[i] = 0; g_probsum[i] = 0.0f; }
}

// ---------------- kernel 1: router --------------------------------------------
__global__ __launch_bounds__(256) void router_kernel(
    const float* __restrict__ x, const float* __restrict__ rw, const float* __restrict__ rb)
{
    int gwarp = (blockIdx.x * blockDim.x + threadIdx.x) >> 5;
    int lane = threadIdx.x & 31;
    if (gwarp >= T_TOKENS) return;
    const float* xr = x + (size_t)gwarp * DM;
    float acc[NE];
#pragma unroll
    for (int e = 0; e < NE; e++) acc[e] = 0.0f;
    for (int k0 = 0; k0 < DM; k0 += 32) {
        float xv = xr[k0 + lane];
        const float* r = rw + (size_t)(k0 + lane) * NE;
        float4 r0 = *(const float4*)r;
        float4 r1 = *(const float4*)(r + 4);
        acc[0] += xv * r0.x; acc[1] += xv * r0.y;
        acc[2] += xv * r0.z; acc[3] += xv * r0.w;
        acc[4] += xv * r1.x; acc[5] += xv * r1.y;
        acc[6] += xv * r1.z; acc[7] += xv * r1.w;
    }
#pragma unroll
    for (int e = 0; e < NE; e++)
#pragma unroll
        for (int off = 16; off > 0; off >>= 1)
            acc[e] += __shfl_xor_sync(0xffffffffu, acc[e], off);
    if (lane == 0) {
        float l[NE], p[NE];
        float m = -1e30f;
#pragma unroll
        for (int e = 0; e < NE; e++) { l[e] = acc[e] + rb[e]; m = fmaxf(m, l[e]); }
        float s = 0.0f;
#pragma unroll
        for (int e = 0; e < NE; e++) { p[e] = expf(l[e] - m); s += p[e]; }
        float inv = 1.0f / s;
#pragma unroll
        for (int e = 0; e < NE; e++) { p[e] *= inv; atomicAdd(&g_probsum[e], p[e]); }
        int i1 = 0; float p1 = p[0];
        int i2 = -1; float p2 = -1.0f;
#pragma unroll
        for (int e = 1; e < NE; e++) {
            if (p[e] > p1) { p2 = p1; i2 = i1; p1 = p[e]; i1 = e; }
            else if (p[e] > p2) { p2 = p[e]; i2 = e; }
        }
        int s1 = atomicAdd(&g_cnt[i1], 1);
        g_idx[i1 * T_TOKENS + s1] = gwarp;
        int s2 = atomicAdd(&g_cnt[i2], 1);
        g_idx[i2 * T_TOKENS + s2] = gwarp;
        g_tok_e[2 * gwarp + 0] = i1; g_tok_slot[2 * gwarp + 0] = s1; g_tok_w[2 * gwarp + 0] = p1;
        g_tok_e[2 * gwarp + 1] = i2; g_tok_slot[2 * gwarp + 1] = s2; g_tok_w[2 * gwarp + 1] = p2;
    }
}

// ---------------- kernel 2: scan + lb_loss ------------------------------------
__global__ void finalize_kernel(float* __restrict__ out) {
    if (threadIdx.x == 0 && blockIdx.x == 0) {
        int base = 0;
        float lb = 0.0f;
        for (int e = 0; e < NE; e++) {
            g_base[e] = base;
            base += g_cnt[e];
            lb += ((float)g_cnt[e] / T_TOKENS) * (g_probsum[e] / T_TOKENS);
        }
        out[(size_t)T_TOKENS * DM] = 0.01f * (float)NE * lb;
    }
}

// ---------------- prep kernels -------------------------------------------------
__global__ __launch_bounds__(256) void prep_x(const float* __restrict__ x) {
    size_t i = ((size_t)blockIdx.x * 256 + threadIdx.x) * 4;
    float4 v = *(const float4*)(x + i);
    uint2 o;
    o.x = pk(v.x, v.y);
    o.y = pk(v.z, v.w);
    *(uint2*)(g_xh + i) = o;
}

__global__ __launch_bounds__(256) void prep_w12(
    const float* __restrict__ w1, const float* __restrict__ w2)
{
    const int kb = blockIdx.x, nblk = blockIdx.y, e = blockIdx.z;
    __shared__ float s1[16][132], s2[16][132];
    const float* w1e = w1 + (size_t)e * DM * DH + (size_t)(kb * 16) * DH + nblk * 128;
    const float* w2e = w2 + (size_t)e * DM * DH + (size_t)(kb * 16) * DH + nblk * 128;
    const int tid = threadIdx.x;
#pragma unroll
    for (int r = 0; r < 2; r++) {
        int t2 = tid + r * 256;
        int k = t2 >> 5, n4 = (t2 & 31) * 4;
        float4 v = *(const float4*)(w1e + (size_t)k * DH + n4);
        s1[k][n4] = v.x; s1[k][n4 + 1] = v.y; s1[k][n4 + 2] = v.z; s1[k][n4 + 3] = v.w;
        v = *(const float4*)(w2e + (size_t)k * DH + n4);
        s2[k][n4] = v.x; s2[k][n4 + 1] = v.y; s2[k][n4 + 2] = v.z; s2[k][n4 + 3] = v.w;
    }
    __syncthreads();
    uint4* dst = g_w12t + ((size_t)((e * 32 + nblk) * 64 + kb)) * 512;
#pragma unroll
    for (int r = 0; r < 2; r++) {
        int slot = tid + r * 256;
        int lane = slot & 31, jn8 = slot >> 5;
        int col = jn8 * 8 + (lane >> 2);
        int k2 = (lane & 3) * 2;
        uint4 o;
        o.x = pk(s1[k2][col], s1[k2 + 1][col]);
        o.y = pk(s1[k2 + 8][col], s1[k2 + 9][col]);
        o.z = pk(s2[k2][col], s2[k2 + 1][col]);
        o.w = pk(s2[k2 + 8][col], s2[k2 + 9][col]);
        dst[slot] = o;
    }
}

__global__ __launch_bounds__(256) void prep_wo(const float* __restrict__ wo) {
    const int kb = blockIdx.x, nblk = blockIdx.y, e = blockIdx.z;
    __shared__ float s[16][132];
    const float* we = wo + (size_t)e * DH * DM + (size_t)(kb * 16) * DM + nblk * 128;
    const int tid = threadIdx.x;
#pragma unroll
    for (int r = 0; r < 2; r++) {
        int t2 = tid + r * 256;
        int k = t2 >> 5, n4 = (t2 & 31) * 4;
        float4 v = *(const float4*)(we + (size_t)k * DM + n4);
        s[k][n4] = v.x; s[k][n4 + 1] = v.y; s[k][n4 + 2] = v.z; s[k][n4 + 3] = v.w;
    }
    __syncthreads();
    uint2* dst = g_wot + ((size_t)((e * 8 + nblk) * 256 + kb)) * 512;
#pragma unroll
    for (int r = 0; r < 2; r++) {
        int slot = tid + r * 256;
        int lane = slot & 31, jn8 = slot >> 5;
        int col = jn8 * 8 + (lane >> 2);
        int k2 = (lane & 3) * 2;
        uint2 o;
        o.x = pk(s[k2][col], s[k2 + 1][col]);
        o.y = pk(s[k2 + 8][col], s[k2 + 9][col]);
        dst[slot] = o;
    }
}

// ---------------- kernel 3: FFN-in (fp16 mma, dual-B, SiLU) -------------------
// 512 thr, tile 128m x 128n x k16 per stage, 5-stage cp.async, 1 barrier/iter
#define FI_STAGE 14336
#define FI_NS 5
#define FI_B 6144
#define FI_TOK (FI_NS * FI_STAGE)
#define FI_BB1 (FI_TOK + 512)
#define FI_BB2 (FI_BB1 + 512)
#define FI_SMEM (FI_BB2 + 512)

__global__ __launch_bounds__(512, 1) void ffn_in_h(
    const float* __restrict__ b1, const float* __restrict__ b2)
{
    const int e = blockIdx.z, nblk = blockIdx.y;
    const int cnt = g_cnt[e];
    const int row0 = blockIdx.x * 128;
    if (row0 >= cnt) return;
    const int n0 = nblk * 128;
    const int base = g_base[e];

    extern __shared__ __align__(16) char smem[];
    const uint32_t sb = smem_u32(smem);
    const int tid = threadIdx.x;
    const int lane = tid & 31, wid = tid >> 5;
    const int wm = (wid & 3) * 32, wn = (wid >> 2) * 32;
    const int g = lane >> 2, tg = lane & 3;

    int* toks = (int*)(smem + FI_TOK);
    float* bb1 = (float*)(smem + FI_BB1);
    float* bb2 = (float*)(smem + FI_BB2);
    if (tid < 128) {
        int r = row0 + tid;
        if (r >= cnt) r = cnt - 1;
        toks[tid] = g_idx[e * T_TOKENS + r];
    } else if (tid < 256) bb1[tid - 128] = b1[e * DH + n0 + (tid - 128)];
    else if (tid < 384)   bb2[tid - 256] = b2[e * DH + n0 + (tid - 256)];
    __syncthreads();

    const char* asrc = nullptr;
    uint32_t adst = 0;
    if (tid < 256) {
        int arow = tid >> 1, ac = tid & 1;
        asrc = (const char*)(g_xh + (size_t)toks[arow] * DM) + ac * 16;
        adst = sb + arow * 48 + ac * 16;
    }
    const char* bsrc = (const char*)(g_w12t + ((size_t)(e * 32 + nblk) * 64) * 512 + tid);
    const uint32_t bdst = sb + FI_B + tid * 16;

    float c1[2][4][4], c2[2][4][4];
#pragma unroll
    for (int i = 0; i < 2; i++)
#pragma unroll
        for (int j = 0; j < 4; j++)
#pragma unroll
            for (int q = 0; q < 4; q++) { c1[i][j][q] = 0.0f; c2[i][j][q] = 0.0f; }

    auto stage = [&](int kt, int buf) {
        uint32_t o = buf * FI_STAGE;
        if (tid < 256) cp16(adst + o, asrc + (size_t)kt * 32);
        cp16(bdst + o, bsrc + (size_t)kt * 8192);
    };

#pragma unroll
    for (int i = 0; i < 4; i++) { stage(i, i); cp_commit(); }

    const uint32_t lrow = lane & 15, lhalf = lane >> 4;
    int ld_buf = 4, rd_buf = 0;
    for (int kt = 0; kt < 64; kt++) {
        cp_wait3();
        __syncthreads();
        if (kt + 4 < 64) stage(kt + 4, ld_buf);
        cp_commit();
        ld_buf = (ld_buf == FI_NS - 1) ? 0 : ld_buf + 1;

        const uint32_t so = rd_buf * FI_STAGE;
        rd_buf = (rd_buf == FI_NS - 1) ? 0 : rd_buf + 1;
        uint32_t a[2][4];
#pragma unroll
        for (int im = 0; im < 2; im++)
            ldm4(a[im], sb + so + (wm + im * 16 + lrow) * 48 + lhalf * 16);
#pragma unroll
        for (int jn = 0; jn < 4; jn++) {
            const char* bp = smem + so + FI_B + ((((wn >> 3) + jn) * 32 + lane) << 4);
            uint4 v = *(const uint4*)bp;
            mma16(c1[0][jn], a[0], v.x, v.y);
            mma16(c1[1][jn], a[1], v.x, v.y);
            mma16(c2[0][jn], a[0], v.z, v.w);
            mma16(c2[1][jn], a[1], v.z, v.w);
        }
    }

#pragma unroll
    for (int im = 0; im < 2; im++) {
#pragma unroll
        for (int jn = 0; jn < 4; jn++) {
            int colL = wn + jn * 8 + 2 * tg;
            float bv1a = bb1[colL], bv1b = bb1[colL + 1];
            float bv2a = bb2[colL], bv2b = bb2[colL + 1];
            int r0 = row0 + wm + im * 16 + g;
            size_t colG = (size_t)n0 + colL;
            if (r0 < cnt) {
                float v1 = c1[im][jn][0] + bv1a, w = c2[im][jn][0] + bv2a;
                float h0 = v1 * w / (1.0f + __expf(-w));
                v1 = c1[im][jn][1] + bv1b; w = c2[im][jn][1] + bv2b;
                float h1 = v1 * w / (1.0f + __expf(-w));
                *(uint32_t*)(g_Hh + (size_t)(base + r0) * DH + colG) = pk(h0, h1);
            }
            int r1 = r0 + 8;
            if (r1 < cnt) {
                float v1 = c1[im][jn][2] + bv1a, w = c2[im][jn][2] + bv2a;
                float h0 = v1 * w / (1.0f + __expf(-w));
                v1 = c1[im][jn][3] + bv1b; w = c2[im][jn][3] + bv2b;
                float h1 = v1 * w / (1.0f + __expf(-w));
                *(uint32_t*)(g_Hh + (size_t)(base + r1) * DH + colG) = pk(h0, h1);
            }
        }
    }
}

// ---------------- kernel 4: FFN-out (fp16 mma) ---------------------------------
#define FO_STAGE 10240
#define FO_NS 5
#define FO_B 6144
#define FO_BB (FO_NS * FO_STAGE)
#define FO_SMEM (FO_BB + 512)

__global__ __launch_bounds__(512, 1) void ffn_out_h(const float* __restrict__ bo) {
    const int e = blockIdx.z, nblk = blockIdx.y;
    const int cnt = g_cnt[e];
    const int row0 = blockIdx.x * 128;
    if (row0 >= cnt) return;
    const int n0 = nblk * 128;
    const int base = g_base[e];

    __shared__ __align__(16) char smem[FO_SMEM];
    const uint32_t sb = smem_u32(smem);
    const int tid = threadIdx.x;
    const int lane = tid & 31, wid = tid >> 5;
    const int wm = (wid & 3) * 32, wn = (wid >> 2) * 32;
    const int g = lane >> 2, tg = lane & 3;

    float* bb = (float*)(smem + FO_BB);
    if (tid < 128) bb[tid] = bo[e * DM + n0 + tid];
    __syncthreads();

    const char* asrc = nullptr;
    uint32_t adst = 0;
    const char* bsrc = nullptr;
    uint32_t bdst = 0;
    if (tid < 256) {
        int arow = tid >> 1, ac = tid & 1;
        int r = row0 + arow;
        if (r >= cnt) r = cnt - 1;
        asrc = (const char*)(g_Hh + (size_t)(base + r) * DH) + ac * 16;
        adst = sb + arow * 48 + ac * 16;
    } else {
        int slot = tid - 256;
        bsrc = (const char*)((const uint4*)g_wot + ((size_t)(e * 8 + nblk) * 256) * 256 + slot);
        bdst = sb + FO_B + slot * 16;
    }

    float c[2][4][4];
#pragma unroll
    for (int i = 0; i < 2; i++)
#pragma unroll
        for (int j = 0; j < 4; j++)
#pragma unroll
            for (int q = 0; q < 4; q++) c[i][j][q] = 0.0f;

    auto stage = [&](int kt, int buf) {
        uint32_t o = buf * FO_STAGE;
        if (tid < 256) cp16(adst + o, asrc + (size_t)kt * 32);
        else           cp16(bdst + o, bsrc + (size_t)kt * 4096);
    };

#pragma unroll
    for (int i = 0; i < 4; i++) { stage(i, i); cp_commit(); }

    const uint32_t lrow = lane & 15, lhalf = lane >> 4;
    int ld_buf = 4, rd_buf = 0;
    for (int kt = 0; kt < 256; kt++) {
        cp_wait3();
        __syncthreads();
        if (kt + 4 < 256) stage(kt + 4, ld_buf);
        cp_commit();
        ld_buf = (ld_buf == FO_NS - 1) ? 0 : ld_buf + 1;

        const uint32_t so = rd_buf * FO_STAGE;
        rd_buf = (rd_buf == FO_NS - 1) ? 0 : rd_buf + 1;
        uint32_t a[2][4];
#pragma unroll
        for (int im = 0; im < 2; im++)
            ldm4(a[im], sb + so + (wm + im * 16 + lrow) * 48 + lhalf * 16);
#pragma unroll
        for (int jn = 0; jn < 4; jn++) {
            const char* bp = smem + so + FO_B + ((((wn >> 3) + jn) * 32 + lane) << 3);
            uint2 v = *(const uint2*)bp;
            mma16(c[0][jn], a[0], v.x, v.y);
            mma16(c[1][jn], a[1], v.x, v.y);
        }
    }

#pragma unroll
    for (int im = 0; im < 2; im++) {
#pragma unroll
        for (int jn = 0; jn < 4; jn++) {
            int colL = wn + jn * 8 + 2 * tg;
            float ba = bb[colL], bbv = bb[colL + 1];
            int r0 = row0 + wm + im * 16 + g;
            size_t colG = (size_t)n0 + colL;
            if (r0 < cnt) {
                float2 o;
                o.x = c[im][jn][0] + ba;
                o.y = c[im][jn][1] + bbv;
                *(float2*)(g_Y + (size_t)(base + r0) * DM + colG) = o;
            }
            int r1 = r0 + 8;
            if (r1 < cnt) {
                float2 o;
                o.x = c[im][jn][2] + ba;
                o.y = c[im][jn][3] + bbv;
                *(float2*)(g_Y + (size_t)(base + r1) * DM + colG) = o;
            }
        }
    }
}

// ---------------- kernel 5: combine --------------------------------------------
__global__ void combine_kernel(float* __restrict__ out) {
    int t = blockIdx.x;
    int tid = threadIdx.x;
    int e1 = g_tok_e[2 * t], e2 = g_tok_e[2 * t + 1];
    float w1v = g_tok_w[2 * t], w2v = g_tok_w[2 * t + 1];
    size_t r1 = (size_t)(g_base[e1] + g_tok_slot[2 * t]) * DM;
    size_t r2 = (size_t)(g_base[e2] + g_tok_slot[2 * t + 1]) * DM;
    float4 a = ((const float4*)(g_Y + r1))[tid];
    float4 b = ((const float4*)(g_Y + r2))[tid];
    float4 o;
    o.x = w1v * a.x + w2v * b.x;
    o.y = w1v * a.y + w2v * b.y;
    o.z = w1v * a.z + w2v * b.z;
    o.w = w1v * a.w + w2v * b.w;
    ((float4*)(out + (size_t)t * DM))[tid] = o;
}

// ---------------- launch -------------------------------------------------------
extern "C" void kernel_launch(void* const* d_in, const int* in_sizes, int n_in,
                              void* d_out, int out_size) {
    (void)in_sizes; (void)n_in; (void)out_size;
    const float* x  = (const float*)d_in[0];
    const float* rw = (const float*)d_in[1];
    const float* rb = (const float*)d_in[2];
    const float* w1 = (const float*)d_in[3];
    const float* b1 = (const float*)d_in[4];
    const float* w2 = (const float*)d_in[5];
    const float* b2 = (const float*)d_in[6];
    const float* wo = (const float*)d_in[7];
    const float* bo = (const float*)d_in[8];
    float* out = (float*)d_out;

    cudaFuncSetAttribute(ffn_in_h, cudaFuncAttributeMaxDynamicSharedMemorySize, FI_SMEM);

    init_kernel<<<1, 32>>>();
    router_kernel<<<512, 256>>>(x, rw, rb);
    finalize_kernel<<<1, 32>>>(out);
    prep_x<<<(T_TOKENS * DM) / 1024, 256>>>(x);
    prep_w12<<<dim3(64, 32, NE), 256>>>(w1, w2);
    prep_wo<<<dim3(256, 8, NE), 256>>>(wo);
    ffn_in_h<<<dim3(T_TOKENS / 128, DH / 128, NE), 512, FI_SMEM>>>(b1, b2);
    ffn_out_h<<<dim3(T_TOKENS / 128, DM / 128, NE), 512>>>(bo);
    combine_kernel<<<T_TOKENS, 256>>>(out);
}

// round 6
// speedup vs baseline: 1.9233x; 1.0223x over previous
#include <cuda_runtime.h>
#include <cuda_fp16.h>
#include <cstdint>

#define T_TOKENS 4096
#define DM 1024
#define DH 4096
#define NE 8

// ---------------- scratch (device globals) -----------------------------------
__device__ int   g_cnt[NE];
__device__ int   g_base[NE];
__device__ float g_probsum[NE];
__device__ int   g_idx[NE * T_TOKENS];
__device__ int   g_tok_e[T_TOKENS * 2];
__device__ int   g_tok_slot[T_TOKENS * 2];
__device__ float g_tok_w[T_TOKENS * 2];
__device__ __half g_xh[(size_t)T_TOKENS * DM];
__device__ __half g_Hh[(size_t)2 * T_TOKENS * DH];
__device__ float  g_Y[(size_t)2 * T_TOKENS * DM];
__device__ uint4  g_w12t[(size_t)NE * 32 * 64 * 512];
__device__ uint2  g_wot[(size_t)NE * 8 * 256 * 512];
// persistent-queue state
__device__ int g_tiles_in[2560];
__device__ int g_tiles_out[640];
__device__ int g_ntiles_in, g_ntiles_out;
__device__ int g_tick_in, g_tick_out;

// ---------------- helpers -----------------------------------------------------
__device__ __forceinline__ uint32_t smem_u32(const void* p) {
    uint32_t a;
    asm("{ .reg .u64 t; cvta.to.shared.u64 t, %1; cvt.u32.u64 %0, t; }" : "=r"(a) : "l"(p));
    return a;
}
__device__ __forceinline__ uint32_t pk(float lo, float hi) {
    __half2 h = __floats2half2_rn(lo, hi);
    return *(uint32_t*)&h;
}
__device__ __forceinline__ void cp16(uint32_t dst, const void* src) {
    asm volatile("cp.async.cg.shared.global [%0], [%1], 16;" :: "r"(dst), "l"(src) : "memory");
}
__device__ __forceinline__ void cp_commit() {
    asm volatile("cp.async.commit_group;" ::: "memory");
}
__device__ __forceinline__ void cp_wait3() {
    asm volatile("cp.async.wait_group 3;" ::: "memory");
}
__device__ __forceinline__ void ldm4(uint32_t a[4], uint32_t addr) {
    asm volatile("ldmatrix.sync.aligned.m8n8.x4.shared.b16 {%0,%1,%2,%3}, [%4];"
                 : "=r"(a[0]), "=r"(a[1]), "=r"(a[2]), "=r"(a[3]) : "r"(addr));
}
__device__ __forceinline__ void mma16(float c[4], const uint32_t a[4],
                                      uint32_t b0, uint32_t b1) {
    asm volatile("mma.sync.aligned.m16n8k16.row.col.f32.f16.f16.f32 "
                 "{%0,%1,%2,%3}, {%4,%5,%6,%7}, {%8,%9}, {%0,%1,%2,%3};"
                 : "+f"(c[0]), "+f"(c[1]), "+f"(c[2]), "+f"(c[3])
                 : "r"(a[0]), "r"(a[1]), "r"(a[2]), "r"(a[3]), "r"(b0), "r"(b1));
}

// ---------------- init --------------------------------------------------------
__global__ void init_kernel() {
    int i = threadIdx.x;
    if (i < NE) { g_cnt[i] = 0; g_probsum[i] = 0.0f; }
    if (i == 0) { g_tick_in = 0; g_tick_out = 0; }
}

// ---------------- router ------------------------------------------------------
__global__ __launch_bounds__(256) void router_kernel(
    const float* __restrict__ x, const float* __restrict__ rw, const float* __restrict__ rb)
{
    int gwarp = (blockIdx.x * blockDim.x + threadIdx.x) >> 5;
    int lane = threadIdx.x & 31;
    if (gwarp >= T_TOKENS) return;
    const float* xr = x + (size_t)gwarp * DM;
    float acc[NE];
#pragma unroll
    for (int e = 0; e < NE; e++) acc[e] = 0.0f;
    for (int k0 = 0; k0 < DM; k0 += 32) {
        float xv = xr[k0 + lane];
        const float* r = rw + (size_t)(k0 + lane) * NE;
        float4 r0 = *(const float4*)r;
        float4 r1 = *(const float4*)(r + 4);
        acc[0] += xv * r0.x; acc[1] += xv * r0.y;
        acc[2] += xv * r0.z; acc[3] += xv * r0.w;
        acc[4] += xv * r1.x; acc[5] += xv * r1.y;
        acc[6] += xv * r1.z; acc[7] += xv * r1.w;
    }
#pragma unroll
    for (int e = 0; e < NE; e++)
#pragma unroll
        for (int off = 16; off > 0; off >>= 1)
            acc[e] += __shfl_xor_sync(0xffffffffu, acc[e], off);
    if (lane == 0) {
        float l[NE], p[NE];
        float m = -1e30f;
#pragma unroll
        for (int e = 0; e < NE; e++) { l[e] = acc[e] + rb[e]; m = fmaxf(m, l[e]); }
        float s = 0.0f;
#pragma unroll
        for (int e = 0; e < NE; e++) { p[e] = expf(l[e] - m); s += p[e]; }
        float inv = 1.0f / s;
#pragma unroll
        for (int e = 0; e < NE; e++) { p[e] *= inv; atomicAdd(&g_probsum[e], p[e]); }
        int i1 = 0; float p1 = p[0];
        int i2 = -1; float p2 = -1.0f;
#pragma unroll
        for (int e = 1; e < NE; e++) {
            if (p[e] > p1) { p2 = p1; i2 = i1; p1 = p[e]; i1 = e; }
            else if (p[e] > p2) { p2 = p[e]; i2 = e; }
        }
        int s1 = atomicAdd(&g_cnt[i1], 1);
        g_idx[i1 * T_TOKENS + s1] = gwarp;
        int s2 = atomicAdd(&g_cnt[i2], 1);
        g_idx[i2 * T_TOKENS + s2] = gwarp;
        g_tok_e[2 * gwarp + 0] = i1; g_tok_slot[2 * gwarp + 0] = s1; g_tok_w[2 * gwarp + 0] = p1;
        g_tok_e[2 * gwarp + 1] = i2; g_tok_slot[2 * gwarp + 1] = s2; g_tok_w[2 * gwarp + 1] = p2;
    }
}

// ---------------- finalize: scan, lb_loss, tile worklists ---------------------
__global__ __launch_bounds__(256) void finalize_kernel(float* __restrict__ out) {
    __shared__ int s_rb[NE], s_ti[NE + 1], s_to[NE + 1];
    const int tid = threadIdx.x;
    if (tid == 0) {
        int base = 0, ti = 0, to = 0;
        float lb = 0.0f;
        for (int e = 0; e < NE; e++) {
            g_base[e] = base;
            base += g_cnt[e];
            lb += ((float)g_cnt[e] / T_TOKENS) * (g_probsum[e] / T_TOKENS);
            int rb = (g_cnt[e] + 127) >> 7;
            s_rb[e] = rb;
            s_ti[e] = ti; s_to[e] = to;
            ti += rb * 32;
            to += rb * 8;
        }
        s_ti[NE] = ti; s_to[NE] = to;
        g_ntiles_in = ti; g_ntiles_out = to;
        out[(size_t)T_TOKENS * DM] = 0.01f * (float)NE * lb;
    }
    __syncthreads();
    const int nti = s_ti[NE], nto = s_to[NE];
    for (int i = tid; i < nti; i += 256) {
        int e = 0;
        while (i >= s_ti[e + 1]) e++;
        int loc = i - s_ti[e];
        int rb = s_rb[e];
        int nblk = loc / rb, r = loc - nblk * rb;
        g_tiles_in[i] = (e << 16) | (nblk << 8) | r;
    }
    for (int i = tid; i < nto; i += 256) {
        int e = 0;
        while (i >= s_to[e + 1]) e++;
        int loc = i - s_to[e];
        int rb = s_rb[e];
        int nblk = loc / rb, r = loc - nblk * rb;
        g_tiles_out[i] = (e << 16) | (nblk << 8) | r;
    }
}

// ---------------- prep kernels -------------------------------------------------
__global__ __launch_bounds__(256) void prep_x(const float* __restrict__ x) {
    size_t i = ((size_t)blockIdx.x * 256 + threadIdx.x) * 4;
    float4 v = *(const float4*)(x + i);
    uint2 o;
    o.x = pk(v.x, v.y);
    o.y = pk(v.z, v.w);
    *(uint2*)(g_xh + i) = o;
}

__global__ __launch_bounds__(256) void prep_w12(
    const float* __restrict__ w1, const float* __restrict__ w2)
{
    const int kb = blockIdx.x, nblk = blockIdx.y, e = blockIdx.z;
    __shared__ float s1[16][132], s2[16][132];
    const float* w1e = w1 + (size_t)e * DM * DH + (size_t)(kb * 16) * DH + nblk * 128;
    const float* w2e = w2 + (size_t)e * DM * DH + (size_t)(kb * 16) * DH + nblk * 128;
    const int tid = threadIdx.x;
#pragma unroll
    for (int r = 0; r < 2; r++) {
        int t2 = tid + r * 256;
        int k = t2 >> 5, n4 = (t2 & 31) * 4;
        float4 v = *(const float4*)(w1e + (size_t)k * DH + n4);
        s1[k][n4] = v.x; s1[k][n4 + 1] = v.y; s1[k][n4 + 2] = v.z; s1[k][n4 + 3] = v.w;
        v = *(const float4*)(w2e + (size_t)k * DH + n4);
        s2[k][n4] = v.x; s2[k][n4 + 1] = v.y; s2[k][n4 + 2] = v.z; s2[k][n4 + 3] = v.w;
    }
    __syncthreads();
    uint4* dst = g_w12t + ((size_t)((e * 32 + nblk) * 64 + kb)) * 512;
#pragma unroll
    for (int r = 0; r < 2; r++) {
        int slot = tid + r * 256;
        int lane = slot & 31, jn8 = slot >> 5;
        int col = jn8 * 8 + (lane >> 2);
        int k2 = (lane & 3) * 2;
        uint4 o;
        o.x = pk(s1[k2][col], s1[k2 + 1][col]);
        o.y = pk(s1[k2 + 8][col], s1[k2 + 9][col]);
        o.z = pk(s2[k2][col], s2[k2 + 1][col]);
        o.w = pk(s2[k2 + 8][col], s2[k2 + 9][col]);
        dst[slot] = o;
    }
}

__global__ __launch_bounds__(256) void prep_wo(const float* __restrict__ wo) {
    const int kb = blockIdx.x, nblk = blockIdx.y, e = blockIdx.z;
    __shared__ float s[16][132];
    const float* we = wo + (size_t)e * DH * DM + (size_t)(kb * 16) * DM + nblk * 128;
    const int tid = threadIdx.x;
#pragma unroll
    for (int r = 0; r < 2; r++) {
        int t2 = tid + r * 256;
        int k = t2 >> 5, n4 = (t2 & 31) * 4;
        float4 v = *(const float4*)(we + (size_t)k * DM + n4);
        s[k][n4] = v.x; s[k][n4 + 1] = v.y; s[k][n4 + 2] = v.z; s[k][n4 + 3] = v.w;
    }
    __syncthreads();
    uint2* dst = g_wot + ((size_t)((e * 8 + nblk) * 256 + kb)) * 512;
#pragma unroll
    for (int r = 0; r < 2; r++) {
        int slot = tid + r * 256;
        int lane = slot & 31, jn8 = slot >> 5;
        int col = jn8 * 8 + (lane >> 2);
        int k2 = (lane & 3) * 2;
        uint2 o;
        o.x = pk(s[k2][col], s[k2 + 1][col]);
        o.y = pk(s[k2 + 8][col], s[k2 + 9][col]);
        dst[slot] = o;
    }
}

// ---------------- FFN-in (persistent, fp16 mma, dual-B, SiLU) -----------------
#define FI_STAGE 14336
#define FI_NS 5
#define FI_B 6144
#define FI_TOK (FI_NS * FI_STAGE)
#define FI_BB1 (FI_TOK + 512)
#define FI_BB2 (FI_BB1 + 512)
#define FI_TILE (FI_BB2 + 512)
#define FI_SMEM (FI_TILE + 16)

__global__ __launch_bounds__(512, 1) void ffn_in_h(
    const float* __restrict__ b1, const float* __restrict__ b2)
{
    extern __shared__ __align__(16) char smem[];
    const uint32_t sb = smem_u32(smem);
    const int tid = threadIdx.x;
    const int lane = tid & 31, wid = tid >> 5;
    const int wm = (wid & 3) * 32, wn = (wid >> 2) * 32;
    const int g = lane >> 2, tg = lane & 3;
    const uint32_t lrow = lane & 15, lhalf = lane >> 4;
    int* s_tile = (int*)(smem + FI_TILE);
    int* toks = (int*)(smem + FI_TOK);
    float* bb1 = (float*)(smem + FI_BB1);
    float* bb2 = (float*)(smem + FI_BB2);

    while (true) {
        if (tid == 0) *s_tile = atomicAdd(&g_tick_in, 1);
        __syncthreads();
        const int t = *s_tile;
        if (t >= g_ntiles_in) break;
        const int w = g_tiles_in[t];
        const int e = w >> 16, nblk = (w >> 8) & 255;
        const int row0 = (w & 255) * 128;
        const int cnt = g_cnt[e];
        const int n0 = nblk * 128;
        const int base = g_base[e];

        if (tid < 128) {
            int r = row0 + tid;
            if (r >= cnt) r = cnt - 1;
            toks[tid] = g_idx[e * T_TOKENS + r];
        } else if (tid < 256) bb1[tid - 128] = b1[e * DH + n0 + (tid - 128)];
        else if (tid < 384)   bb2[tid - 256] = b2[e * DH + n0 + (tid - 256)];
        __syncthreads();

        const char* asrc = nullptr;
        uint32_t adst = 0;
        if (tid < 256) {
            int arow = tid >> 1, ac = tid & 1;
            asrc = (const char*)(g_xh + (size_t)toks[arow] * DM) + ac * 16;
            adst = sb + arow * 48 + ac * 16;
        }
        const char* bsrc = (const char*)(g_w12t + ((size_t)(e * 32 + nblk) * 64) * 512 + tid);
        const uint32_t bdst = sb + FI_B + tid * 16;

        float c1[2][4][4], c2[2][4][4];
#pragma unroll
        for (int i = 0; i < 2; i++)
#pragma unroll
            for (int j = 0; j < 4; j++)
#pragma unroll
                for (int q = 0; q < 4; q++) { c1[i][j][q] = 0.0f; c2[i][j][q] = 0.0f; }

        auto stage = [&](int kt, int buf) {
            uint32_t o = buf * FI_STAGE;
            if (tid < 256) cp16(adst + o, asrc + (size_t)kt * 32);
            cp16(bdst + o, bsrc + (size_t)kt * 8192);
        };

#pragma unroll
        for (int i = 0; i < 4; i++) { stage(i, i); cp_commit(); }

        int ld_buf = 4, rd_buf = 0;
        for (int kt = 0; kt < 64; kt++) {
            cp_wait3();
            __syncthreads();
            if (kt + 4 < 64) stage(kt + 4, ld_buf);
            cp_commit();
            ld_buf = (ld_buf == FI_NS - 1) ? 0 : ld_buf + 1;

            const uint32_t so = rd_buf * FI_STAGE;
            rd_buf = (rd_buf == FI_NS - 1) ? 0 : rd_buf + 1;
            uint32_t a[2][4];
#pragma unroll
            for (int im = 0; im < 2; im++)
                ldm4(a[im], sb + so + (wm + im * 16 + lrow) * 48 + lhalf * 16);
#pragma unroll
            for (int jn = 0; jn < 4; jn++) {
                const char* bp = smem + so + FI_B + ((((wn >> 3) + jn) * 32 + lane) << 4);
                uint4 v = *(const uint4*)bp;
                mma16(c1[0][jn], a[0], v.x, v.y);
                mma16(c1[1][jn], a[1], v.x, v.y);
                mma16(c2[0][jn], a[0], v.z, v.w);
                mma16(c2[1][jn], a[1], v.z, v.w);
            }
        }

#pragma unroll
        for (int im = 0; im < 2; im++) {
#pragma unroll
            for (int jn = 0; jn < 4; jn++) {
                int colL = wn + jn * 8 + 2 * tg;
                float bv1a = bb1[colL], bv1b = bb1[colL + 1];
                float bv2a = bb2[colL], bv2b = bb2[colL + 1];
                int r0 = row0 + wm + im * 16 + g;
                size_t colG = (size_t)n0 + colL;
                if (r0 < cnt) {
                    float v1 = c1[im][jn][0] + bv1a, ww = c2[im][jn][0] + bv2a;
                    float h0 = v1 * ww / (1.0f + __expf(-ww));
                    v1 = c1[im][jn][1] + bv1b; ww = c2[im][jn][1] + bv2b;
                    float h1 = v1 * ww / (1.0f + __expf(-ww));
                    *(uint32_t*)(g_Hh + (size_t)(base + r0) * DH + colG) = pk(h0, h1);
                }
                int r1 = r0 + 8;
                if (r1 < cnt) {
                    float v1 = c1[im][jn][2] + bv1a, ww = c2[im][jn][2] + bv2a;
                    float h0 = v1 * ww / (1.0f + __expf(-ww));
                    v1 = c1[im][jn][3] + bv1b; ww = c2[im][jn][3] + bv2b;
                    float h1 = v1 * ww / (1.0f + __expf(-ww));
                    *(uint32_t*)(g_Hh + (size_t)(base + r1) * DH + colG) = pk(h0, h1);
                }
            }
        }
    }
}

// ---------------- FFN-out (persistent, fp16 mma) -------------------------------
#define FO_STAGE 10240
#define FO_NS 5
#define FO_B 6144
#define FO_BB (FO_NS * FO_STAGE)
#define FO_TILE (FO_BB + 512)
#define FO_SMEM (FO_TILE + 16)

__global__ __launch_bounds__(512, 1) void ffn_out_h(const float* __restrict__ bo) {
    __shared__ __align__(16) char smem[FO_SMEM];
    const uint32_t sb = smem_u32(smem);
    const int tid = threadIdx.x;
    const int lane = tid & 31, wid = tid >> 5;
    const int wm = (wid & 3) * 32, wn = (wid >> 2) * 32;
    const int g = lane >> 2, tg = lane & 3;
    const uint32_t lrow = lane & 15, lhalf = lane >> 4;
    int* s_tile = (int*)(smem + FO_TILE);
    float* bb = (float*)(smem + FO_BB);

    while (true) {
        if (tid == 0) *s_tile = atomicAdd(&g_tick_out, 1);
        __syncthreads();
        const int t = *s_tile;
        if (t >= g_ntiles_out) break;
        const int w = g_tiles_out[t];
        const int e = w >> 16, nblk = (w >> 8) & 255;
        const int row0 = (w & 255) * 128;
        const int cnt = g_cnt[e];
        const int n0 = nblk * 128;
        const int base = g_base[e];

        if (tid < 128) bb[tid] = bo[e * DM + n0 + tid];
        __syncthreads();

        const char* asrc = nullptr;
        uint32_t adst = 0;
        const char* bsrc = nullptr;
        uint32_t bdst = 0;
        if (tid < 256) {
            int arow = tid >> 1, ac = tid & 1;
            int r = row0 + arow;
            if (r >= cnt) r = cnt - 1;
            asrc = (const char*)(g_Hh + (size_t)(base + r) * DH) + ac * 16;
            adst = sb + arow * 48 + ac * 16;
        } else {
            int slot = tid - 256;
            bsrc = (const char*)((const uint4*)g_wot + ((size_t)(e * 8 + nblk) * 256) * 256 + slot);
            bdst = sb + FO_B + slot * 16;
        }

        float c[2][4][4];
#pragma unroll
        for (int i = 0; i < 2; i++)
#pragma unroll
            for (int j = 0; j < 4; j++)
#pragma unroll
                for (int q = 0; q < 4; q++) c[i][j][q] = 0.0f;

        auto stage = [&](int kt, int buf) {
            uint32_t o = buf * FO_STAGE;
            if (tid < 256) cp16(adst + o, asrc + (size_t)kt * 32);
            else           cp16(bdst + o, bsrc + (size_t)kt * 4096);
        };

#pragma unroll
        for (int i = 0; i < 4; i++) { stage(i, i); cp_commit(); }

        int ld_buf = 4, rd_buf = 0;
        for (int kt = 0; kt < 256; kt++) {
            cp_wait3();
            __syncthreads();
            if (kt + 4 < 256) stage(kt + 4, ld_buf);
            cp_commit();
            ld_buf = (ld_buf == FO_NS - 1) ? 0 : ld_buf + 1;

            const uint32_t so = rd_buf * FO_STAGE;
            rd_buf = (rd_buf == FO_NS - 1) ? 0 : rd_buf + 1;
            uint32_t a[2][4];
#pragma unroll
            for (int im = 0; im < 2; im++)
                ldm4(a[im], sb + so + (wm + im * 16 + lrow) * 48 + lhalf * 16);
#pragma unroll
            for (int jn = 0; jn < 4; jn++) {
                const char* bp = smem + so + FO_B + ((((wn >> 3) + jn) * 32 + lane) << 3);
                uint2 v = *(const uint2*)bp;
                mma16(c[0][jn], a[0], v.x, v.y);
                mma16(c[1][jn], a[1], v.x, v.y);
            }
        }

#pragma unroll
        for (int im = 0; im < 2; im++) {
#pragma unroll
            for (int jn = 0; jn < 4; jn++) {
                int colL = wn + jn * 8 + 2 * tg;
                float ba = bb[colL], bbv = bb[colL + 1];
                int r0 = row0 + wm + im * 16 + g;
                size_t colG = (size_t)n0 + colL;
                if (r0 < cnt) {
                    float2 o;
                    o.x = c[im][jn][0] + ba;
                    o.y = c[im][jn][1] + bbv;
                    *(float2*)(g_Y + (size_t)(base + r0) * DM + colG) = o;
                }
                int r1 = r0 + 8;
                if (r1 < cnt) {
                    float2 o;
                    o.x = c[im][jn][2] + ba;
                    o.y = c[im][jn][3] + bbv;
                    *(float2*)(g_Y + (size_t)(base + r1) * DM + colG) = o;
                }
            }
        }
    }
}

// ---------------- combine ------------------------------------------------------
__global__ void combine_kernel(float* __restrict__ out) {
    int t = blockIdx.x;
    int tid = threadIdx.x;
    int e1 = g_tok_e[2 * t], e2 = g_tok_e[2 * t + 1];
    float w1v = g_tok_w[2 * t], w2v = g_tok_w[2 * t + 1];
    size_t r1 = (size_t)(g_base[e1] + g_tok_slot[2 * t]) * DM;
    size_t r2 = (size_t)(g_base[e2] + g_tok_slot[2 * t + 1]) * DM;
    float4 a = ((const float4*)(g_Y + r1))[tid];
    float4 b = ((const float4*)(g_Y + r2))[tid];
    float4 o;
    o.x = w1v * a.x + w2v * b.x;
    o.y = w1v * a.y + w2v * b.y;
    o.z = w1v * a.z + w2v * b.z;
    o.w = w1v * a.w + w2v * b.w;
    ((float4*)(out + (size_t)t * DM))[tid] = o;
}

// ---------------- launch -------------------------------------------------------
extern "C" void kernel_launch(void* const* d_in, const int* in_sizes, int n_in,
                              void* d_out, int out_size) {
    (void)in_sizes; (void)n_in; (void)out_size;
    const float* x  = (const float*)d_in[0];
    const float* rw = (const float*)d_in[1];
    const float* rb = (const float*)d_in[2];
    const float* w1 = (const float*)d_in[3];
    const float* b1 = (const float*)d_in[4];
    const float* w2 = (const float*)d_in[5];
    const float* b2 = (const float*)d_in[6];
    const float* wo = (const float*)d_in[7];
    const float* bo = (const float*)d_in[8];
    float* out = (float*)d_out;

    cudaFuncSetAttribute(ffn_in_h, cudaFuncAttributeMaxDynamicSharedMemorySize, FI_SMEM);

    prep_x<<<(T_TOKENS * DM) / 1024, 256>>>(x);
    prep_w12<<<dim3(64, 32, NE), 256>>>(w1, w2);
    init_kernel<<<1, 32>>>();
    router_kernel<<<512, 256>>>(x, rw, rb);
    finalize_kernel<<<1, 256>>>(out);
    ffn_in_h<<<152, 512, FI_SMEM>>>(b1, b2);
    prep_wo<<<dim3(256, 8, NE), 256>>>(wo);
    ffn_out_h<<<152, 512>>>(bo);
    combine_kernel<<<T_TOKENS, 256>>>(out);
}

// round 7
// speedup vs baseline: 1.9315x; 1.0043x over previous
#include <cuda_runtime.h>
#include <cuda_fp16.h>
#include <cstdint>

#define T_TOKENS 4096
#define DM 1024
#define DH 4096
#define NE 8

// ---------------- scratch (device globals) -----------------------------------
__device__ int   g_cnt[NE];
__device__ int   g_base[NE];
__device__ float g_probsum[NE];
__device__ int   g_idx[NE * T_TOKENS];
__device__ int   g_tok_e[T_TOKENS * 2];
__device__ int   g_tok_slot[T_TOKENS * 2];
__device__ float g_tok_w[T_TOKENS * 2];
__device__ __half g_xh[(size_t)T_TOKENS * DM];
__device__ __half g_Hh[(size_t)2 * T_TOKENS * DH];
__device__ float  g_Y[(size_t)2 * T_TOKENS * DM];
__device__ uint4  g_w12t[(size_t)NE * 32 * 64 * 512];
__device__ uint2  g_wot[(size_t)NE * 8 * 256 * 512];
// persistent-queue state
__device__ int g_tiles_in[2560];
__device__ int g_tiles_out[640];
__device__ int g_ntiles_in, g_ntiles_out;
__device__ int g_tick_in, g_tick_out;

// ---------------- helpers -----------------------------------------------------
__device__ __forceinline__ uint32_t smem_u32(const void* p) {
    uint32_t a;
    asm("{ .reg .u64 t; cvta.to.shared.u64 t, %1; cvt.u32.u64 %0, t; }" : "=r"(a) : "l"(p));
    return a;
}
__device__ __forceinline__ uint32_t pk(float lo, float hi) {
    __half2 h = __floats2half2_rn(lo, hi);
    return *(uint32_t*)&h;
}
__device__ __forceinline__ void cp16(uint32_t dst, const void* src) {
    asm volatile("cp.async.cg.shared.global [%0], [%1], 16;" :: "r"(dst), "l"(src) : "memory");
}
__device__ __forceinline__ void cp_commit() {
    asm volatile("cp.async.commit_group;" ::: "memory");
}
__device__ __forceinline__ void cp_wait3() {
    asm volatile("cp.async.wait_group 3;" ::: "memory");
}
__device__ __forceinline__ void ldm4(uint32_t a[4], uint32_t addr) {
    asm volatile("ldmatrix.sync.aligned.m8n8.x4.shared.b16 {%0,%1,%2,%3}, [%4];"
                 : "=r"(a[0]), "=r"(a[1]), "=r"(a[2]), "=r"(a[3]) : "r"(addr));
}
__device__ __forceinline__ void mma16(float c[4], const uint32_t a[4],
                                      uint32_t b0, uint32_t b1) {
    asm volatile("mma.sync.aligned.m16n8k16.row.col.f32.f16.f16.f32 "
                 "{%0,%1,%2,%3}, {%4,%5,%6,%7}, {%8,%9}, {%0,%1,%2,%3};"
                 : "+f"(c[0]), "+f"(c[1]), "+f"(c[2]), "+f"(c[3])
                 : "r"(a[0]), "r"(a[1]), "r"(a[2]), "r"(a[3]), "r"(b0), "r"(b1));
}

// ---------------- init --------------------------------------------------------
__global__ void init_kernel() {
    int i = threadIdx.x;
    if (i < NE) { g_cnt[i] = 0; g_probsum[i] = 0.0f; }
    if (i == 0) { g_tick_in = 0; g_tick_out = 0; }
}

// ---------------- fused router + x fp16 conversion ----------------------------
// 256 thr = 8 warps = 8 tokens/block; rw transposed in smem; float4 x loads.
__global__ __launch_bounds__(256) void router_prep(
    const float* __restrict__ x, const float* __restrict__ rw, const float* __restrict__ rb)
{
    __shared__ float s_rwT[NE * DM];   // [e][k], 32 KB
    const int tid = threadIdx.x;
    for (int i = tid; i < NE * DM; i += 256) {
        int k = i >> 3, e = i & 7;
        s_rwT[e * DM + k] = rw[i];
    }
    __syncthreads();

    const int lane = tid & 31, wid = tid >> 5;
    const int t = blockIdx.x * 8 + wid;
    const float4* xr = (const float4*)(x + (size_t)t * DM);

    float acc[NE];
#pragma unroll
    for (int e = 0; e < NE; e++) acc[e] = 0.0f;

#pragma unroll
    for (int it = 0; it < 8; it++) {
        const int k4 = it * 32 + lane;
        float4 v = xr[k4];
        uint2 o;
        o.x = pk(v.x, v.y);
        o.y = pk(v.z, v.w);
        *(uint2*)(g_xh + (size_t)t * DM + k4 * 4) = o;
#pragma unroll
        for (int e = 0; e < NE; e++) {
            float4 r = *(const float4*)(s_rwT + e * DM + k4 * 4);
            acc[e] += v.x * r.x + v.y * r.y + v.z * r.z + v.w * r.w;
        }
    }
#pragma unroll
    for (int e = 0; e < NE; e++)
#pragma unroll
        for (int off = 16; off > 0; off >>= 1)
            acc[e] += __shfl_xor_sync(0xffffffffu, acc[e], off);

    if (lane == 0) {
        float l[NE], p[NE];
        float m = -1e30f;
#pragma unroll
        for (int e = 0; e < NE; e++) { l[e] = acc[e] + rb[e]; m = fmaxf(m, l[e]); }
        float s = 0.0f;
#pragma unroll
        for (int e = 0; e < NE; e++) { p[e] = expf(l[e] - m); s += p[e]; }
        float inv = 1.0f / s;
#pragma unroll
        for (int e = 0; e < NE; e++) { p[e] *= inv; atomicAdd(&g_probsum[e], p[e]); }
        int i1 = 0; float p1 = p[0];
        int i2 = -1; float p2 = -1.0f;
#pragma unroll
        for (int e = 1; e < NE; e++) {
            if (p[e] > p1) { p2 = p1; i2 = i1; p1 = p[e]; i1 = e; }
            else if (p[e] > p2) { p2 = p[e]; i2 = e; }
        }
        int s1 = atomicAdd(&g_cnt[i1], 1);
        g_idx[i1 * T_TOKENS + s1] = t;
        int s2 = atomicAdd(&g_cnt[i2], 1);
        g_idx[i2 * T_TOKENS + s2] = t;
        g_tok_e[2 * t + 0] = i1; g_tok_slot[2 * t + 0] = s1; g_tok_w[2 * t + 0] = p1;
        g_tok_e[2 * t + 1] = i2; g_tok_slot[2 * t + 1] = s2; g_tok_w[2 * t + 1] = p2;
    }
}

// ---------------- finalize: scan, lb_loss, tile worklists ---------------------
__global__ __launch_bounds__(256) void finalize_kernel(float* __restrict__ out) {
    __shared__ int s_rb[NE], s_ti[NE + 1], s_to[NE + 1];
    const int tid = threadIdx.x;
    if (tid == 0) {
        int base = 0, ti = 0, to = 0;
        float lb = 0.0f;
        for (int e = 0; e < NE; e++) {
            g_base[e] = base;
            base += g_cnt[e];
            lb += ((float)g_cnt[e] / T_TOKENS) * (g_probsum[e] / T_TOKENS);
            int rb = (g_cnt[e] + 127) >> 7;
            s_rb[e] = rb;
            s_ti[e] = ti; s_to[e] = to;
            ti += rb * 32;
            to += rb * 8;
        }
        s_ti[NE] = ti; s_to[NE] = to;
        g_ntiles_in = ti; g_ntiles_out = to;
        out[(size_t)T_TOKENS * DM] = 0.01f * (float)NE * lb;
    }
    __syncthreads();
    const int nti = s_ti[NE], nto = s_to[NE];
    for (int i = tid; i < nti; i += 256) {
        int e = 0;
        while (i >= s_ti[e + 1]) e++;
        int loc = i - s_ti[e];
        int rb = s_rb[e];
        int nblk = loc / rb, r = loc - nblk * rb;
        g_tiles_in[i] = (e << 16) | (nblk << 8) | r;
    }
    for (int i = tid; i < nto; i += 256) {
        int e = 0;
        while (i >= s_to[e + 1]) e++;
        int loc = i - s_to[e];
        int rb = s_rb[e];
        int nblk = loc / rb, r = loc - nblk * rb;
        g_tiles_out[i] = (e << 16) | (nblk << 8) | r;
    }
}

// ---------------- weight prep --------------------------------------------------
__global__ __launch_bounds__(256) void prep_w12(
    const float* __restrict__ w1, const float* __restrict__ w2)
{
    const int kb = blockIdx.x, nblk = blockIdx.y, e = blockIdx.z;
    __shared__ float s1[16][132], s2[16][132];
    const float* w1e = w1 + (size_t)e * DM * DH + (size_t)(kb * 16) * DH + nblk * 128;
    const float* w2e = w2 + (size_t)e * DM * DH + (size_t)(kb * 16) * DH + nblk * 128;
    const int tid = threadIdx.x;
#pragma unroll
    for (int r = 0; r < 2; r++) {
        int t2 = tid + r * 256;
        int k = t2 >> 5, n4 = (t2 & 31) * 4;
        float4 v = *(const float4*)(w1e + (size_t)k * DH + n4);
        s1[k][n4] = v.x; s1[k][n4 + 1] = v.y; s1[k][n4 + 2] = v.z; s1[k][n4 + 3] = v.w;
        v = *(const float4*)(w2e + (size_t)k * DH + n4);
        s2[k][n4] = v.x; s2[k][n4 + 1] = v.y; s2[k][n4 + 2] = v.z; s2[k][n4 + 3] = v.w;
    }
    __syncthreads();
    uint4* dst = g_w12t + ((size_t)((e * 32 + nblk) * 64 + kb)) * 512;
#pragma unroll
    for (int r = 0; r < 2; r++) {
        int slot = tid + r * 256;
        int lane = slot & 31, jn8 = slot >> 5;
        int col = jn8 * 8 + (lane >> 2);
        int k2 = (lane & 3) * 2;
        uint4 o;
        o.x = pk(s1[k2][col], s1[k2 + 1][col]);
        o.y = pk(s1[k2 + 8][col], s1[k2 + 9][col]);
        o.z = pk(s2[k2][col], s2[k2 + 1][col]);
        o.w = pk(s2[k2 + 8][col], s2[k2 + 9][col]);
        dst[slot] = o;
    }
}

__global__ __launch_bounds__(256) void prep_wo(const float* __restrict__ wo) {
    const int kb = blockIdx.x, nblk = blockIdx.y, e = blockIdx.z;
    __shared__ float s[16][132];
    const float* we = wo + (size_t)e * DH * DM + (size_t)(kb * 16) * DM + nblk * 128;
    const int tid = threadIdx.x;
#pragma unroll
    for (int r = 0; r < 2; r++) {
        int t2 = tid + r * 256;
        int k = t2 >> 5, n4 = (t2 & 31) * 4;
        float4 v = *(const float4*)(we + (size_t)k * DM + n4);
        s[k][n4] = v.x; s[k][n4 + 1] = v.y; s[k][n4 + 2] = v.z; s[k][n4 + 3] = v.w;
    }
    __syncthreads();
    uint2* dst = g_wot + ((size_t)((e * 8 + nblk) * 256 + kb)) * 512;
#pragma unroll
    for (int r = 0; r < 2; r++) {
        int slot = tid + r * 256;
        int lane = slot & 31, jn8 = slot >> 5;
        int col = jn8 * 8 + (lane >> 2);
        int k2 = (lane & 3) * 2;
        uint2 o;
        o.x = pk(s[k2][col], s[k2 + 1][col]);
        o.y = pk(s[k2 + 8][col], s[k2 + 9][col]);
        dst[slot] = o;
    }
}

// ---------------- FFN-in (persistent, fp16 mma, dual-B, SiLU) -----------------
#define FI_STAGE 14336
#define FI_NS 5
#define FI_B 6144
#define FI_TOK (FI_NS * FI_STAGE)
#define FI_BB1 (FI_TOK + 512)
#define FI_BB2 (FI_BB1 + 512)
#define FI_TILE (FI_BB2 + 512)
#define FI_SMEM (FI_TILE + 16)

__global__ __launch_bounds__(512, 1) void ffn_in_h(
    const float* __restrict__ b1, const float* __restrict__ b2)
{
    extern __shared__ __align__(16) char smem[];
    const uint32_t sb = smem_u32(smem);
    const int tid = threadIdx.x;
    const int lane = tid & 31, wid = tid >> 5;
    const int wm = (wid & 3) * 32, wn = (wid >> 2) * 32;
    const int g = lane >> 2, tg = lane & 3;
    const uint32_t lrow = lane & 15, lhalf = lane >> 4;
    int* s_tile = (int*)(smem + FI_TILE);
    int* toks = (int*)(smem + FI_TOK);
    float* bb1 = (float*)(smem + FI_BB1);
    float* bb2 = (float*)(smem + FI_BB2);

    while (true) {
        if (tid == 0) *s_tile = atomicAdd(&g_tick_in, 1);
        __syncthreads();
        const int t = *s_tile;
        if (t >= g_ntiles_in) break;
        const int w = g_tiles_in[t];
        const int e = w >> 16, nblk = (w >> 8) & 255;
        const int row0 = (w & 255) * 128;
        const int cnt = g_cnt[e];
        const int n0 = nblk * 128;
        const int base = g_base[e];

        if (tid < 128) {
            int r = row0 + tid;
            if (r >= cnt) r = cnt - 1;
            toks[tid] = g_idx[e * T_TOKENS + r];
        } else if (tid < 256) bb1[tid - 128] = b1[e * DH + n0 + (tid - 128)];
        else if (tid < 384)   bb2[tid - 256] = b2[e * DH + n0 + (tid - 256)];
        __syncthreads();

        const char* asrc = nullptr;
        uint32_t adst = 0;
        if (tid < 256) {
            int arow = tid >> 1, ac = tid & 1;
            asrc = (const char*)(g_xh + (size_t)toks[arow] * DM) + ac * 16;
            adst = sb + arow * 48 + ac * 16;
        }
        const char* bsrc = (const char*)(g_w12t + ((size_t)(e * 32 + nblk) * 64) * 512 + tid);
        const uint32_t bdst = sb + FI_B + tid * 16;

        float c1[2][4][4], c2[2][4][4];
#pragma unroll
        for (int i = 0; i < 2; i++)
#pragma unroll
            for (int j = 0; j < 4; j++)
#pragma unroll
                for (int q = 0; q < 4; q++) { c1[i][j][q] = 0.0f; c2[i][j][q] = 0.0f; }

        auto stage = [&](int kt, int buf) {
            uint32_t o = buf * FI_STAGE;
            if (tid < 256) cp16(adst + o, asrc + (size_t)kt * 32);
            cp16(bdst + o, bsrc + (size_t)kt * 8192);
        };

#pragma unroll
        for (int i = 0; i < 4; i++) { stage(i, i); cp_commit(); }

        int ld_buf = 4, rd_buf = 0;
        for (int kt = 0; kt < 64; kt++) {
            cp_wait3();
            __syncthreads();
            if (kt + 4 < 64) stage(kt + 4, ld_buf);
            cp_commit();
            ld_buf = (ld_buf == FI_NS - 1) ? 0 : ld_buf + 1;

            const uint32_t so = rd_buf * FI_STAGE;
            rd_buf = (rd_buf == FI_NS - 1) ? 0 : rd_buf + 1;
            uint32_t a[2][4];
#pragma unroll
            for (int im = 0; im < 2; im++)
                ldm4(a[im], sb + so + (wm + im * 16 + lrow) * 48 + lhalf * 16);
#pragma unroll
            for (int jn = 0; jn < 4; jn++) {
                const char* bp = smem + so + FI_B + ((((wn >> 3) + jn) * 32 + lane) << 4);
                uint4 v = *(const uint4*)bp;
                mma16(c1[0][jn], a[0], v.x, v.y);
                mma16(c1[1][jn], a[1], v.x, v.y);
                mma16(c2[0][jn], a[0], v.z, v.w);
                mma16(c2[1][jn], a[1], v.z, v.w);
            }
        }

#pragma unroll
        for (int im = 0; im < 2; im++) {
#pragma unroll
            for (int jn = 0; jn < 4; jn++) {
                int colL = wn + jn * 8 + 2 * tg;
                float bv1a = bb1[colL], bv1b = bb1[colL + 1];
                float bv2a = bb2[colL], bv2b = bb2[colL + 1];
                int r0 = row0 + wm + im * 16 + g;
                size_t colG = (size_t)n0 + colL;
                if (r0 < cnt) {
                    float v1 = c1[im][jn][0] + bv1a, ww = c2[im][jn][0] + bv2a;
                    float h0 = v1 * ww / (1.0f + __expf(-ww));
                    v1 = c1[im][jn][1] + bv1b; ww = c2[im][jn][1] + bv2b;
                    float h1 = v1 * ww / (1.0f + __expf(-ww));
                    *(uint32_t*)(g_Hh + (size_t)(base + r0) * DH + colG) = pk(h0, h1);
                }
                int r1 = r0 + 8;
                if (r1 < cnt) {
                    float v1 = c1[im][jn][2] + bv1a, ww = c2[im][jn][2] + bv2a;
                    float h0 = v1 * ww / (1.0f + __expf(-ww));
                    v1 = c1[im][jn][3] + bv1b; ww = c2[im][jn][3] + bv2b;
                    float h1 = v1 * ww / (1.0f + __expf(-ww));
                    *(uint32_t*)(g_Hh + (size_t)(base + r1) * DH + colG) = pk(h0, h1);
                }
            }
        }
    }
}

// ---------------- FFN-out (persistent, fp16 mma) -------------------------------
#define FO_STAGE 10240
#define FO_NS 5
#define FO_B 6144
#define FO_BB (FO_NS * FO_STAGE)
#define FO_TILE (FO_BB + 512)
#define FO_SMEM (FO_TILE + 16)

__global__ __launch_bounds__(512, 1) void ffn_out_h(const float* __restrict__ bo) {
    __shared__ __align__(16) char smem[FO_SMEM];
    const uint32_t sb = smem_u32(smem);
    const int tid = threadIdx.x;
    const int lane = tid & 31, wid = tid >> 5;
    const int wm = (wid & 3) * 32, wn = (wid >> 2) * 32;
    const int g = lane >> 2, tg = lane & 3;
    const uint32_t lrow = lane & 15, lhalf = lane >> 4;
    int* s_tile = (int*)(smem + FO_TILE);
    float* bb = (float*)(smem + FO_BB);

    while (true) {
        if (tid == 0) *s_tile = atomicAdd(&g_tick_out, 1);
        __syncthreads();
        const int t = *s_tile;
        if (t >= g_ntiles_out) break;
        const int w = g_tiles_out[t];
        const int e = w >> 16, nblk = (w >> 8) & 255;
        const int row0 = (w & 255) * 128;
        const int cnt = g_cnt[e];
        const int n0 = nblk * 128;
        const int base = g_base[e];

        if (tid < 128) bb[tid] = bo[e * DM + n0 + tid];
        __syncthreads();

        const char* asrc = nullptr;
        uint32_t adst = 0;
        const char* bsrc = nullptr;
        uint32_t bdst = 0;
        if (tid < 256) {
            int arow = tid >> 1, ac = tid & 1;
            int r = row0 + arow;
            if (r >= cnt) r = cnt - 1;
            asrc = (const char*)(g_Hh + (size_t)(base + r) * DH) + ac * 16;
            adst = sb + arow * 48 + ac * 16;
        } else {
            int slot = tid - 256;
            bsrc = (const char*)((const uint4*)g_wot + ((size_t)(e * 8 + nblk) * 256) * 256 + slot);
            bdst = sb + FO_B + slot * 16;
        }

        float c[2][4][4];
#pragma unroll
        for (int i = 0; i < 2; i++)
#pragma unroll
            for (int j = 0; j < 4; j++)
#pragma unroll
                for (int q = 0; q < 4; q++) c[i][j][q] = 0.0f;

        auto stage = [&](int kt, int buf) {
            uint32_t o = buf * FO_STAGE;
            if (tid < 256) cp16(adst + o, asrc + (size_t)kt * 32);
            else           cp16(bdst + o, bsrc + (size_t)kt * 4096);
        };

#pragma unroll
        for (int i = 0; i < 4; i++) { stage(i, i); cp_commit(); }

        int ld_buf = 4, rd_buf = 0;
        for (int kt = 0; kt < 256; kt++) {
            cp_wait3();
            __syncthreads();
            if (kt + 4 < 256) stage(kt + 4, ld_buf);
            cp_commit();
            ld_buf = (ld_buf == FO_NS - 1) ? 0 : ld_buf + 1;

            const uint32_t so = rd_buf * FO_STAGE;
            rd_buf = (rd_buf == FO_NS - 1) ? 0 : rd_buf + 1;
            uint32_t a[2][4];
#pragma unroll
            for (int im = 0; im < 2; im++)
                ldm4(a[im], sb + so + (wm + im * 16 + lrow) * 48 + lhalf * 16);
#pragma unroll
            for (int jn = 0; jn < 4; jn++) {
                const char* bp = smem + so + FO_B + ((((wn >> 3) + jn) * 32 + lane) << 3);
                uint2 v = *(const uint2*)bp;
                mma16(c[0][jn], a[0], v.x, v.y);
                mma16(c[1][jn], a[1], v.x, v.y);
            }
        }

#pragma unroll
        for (int im = 0; im < 2; im++) {
#pragma unroll
            for (int jn = 0; jn < 4; jn++) {
                int colL = wn + jn * 8 + 2 * tg;
                float ba = bb[colL], bbv = bb[colL + 1];
                int r0 = row0 + wm + im * 16 + g;
                size_t colG = (size_t)n0 + colL;
                if (r0 < cnt) {
                    float2 o;
                    o.x = c[im][jn][0] + ba;
                    o.y = c[im][jn][1] + bbv;
                    *(float2*)(g_Y + (size_t)(base + r0) * DM + colG) = o;
                }
                int r1 = r0 + 8;
                if (r1 < cnt) {
                    float2 o;
                    o.x = c[im][jn][2] + ba;
                    o.y = c[im][jn][3] + bbv;
                    *(float2*)(g_Y + (size_t)(base + r1) * DM + colG) = o;
                }
            }
        }
    }
}

// ---------------- combine ------------------------------------------------------
__global__ void combine_kernel(float* __restrict__ out) {
    int t = blockIdx.x;
    int tid = threadIdx.x;
    int e1 = g_tok_e[2 * t], e2 = g_tok_e[2 * t + 1];
    float w1v = g_tok_w[2 * t], w2v = g_tok_w[2 * t + 1];
    size_t r1 = (size_t)(g_base[e1] + g_tok_slot[2 * t]) * DM;
    size_t r2 = (size_t)(g_base[e2] + g_tok_slot[2 * t + 1]) * DM;
    float4 a = ((const float4*)(g_Y + r1))[tid];
    float4 b = ((const float4*)(g_Y + r2))[tid];
    float4 o;
    o.x = w1v * a.x + w2v * b.x;
    o.y = w1v * a.y + w2v * b.y;
    o.z = w1v * a.z + w2v * b.z;
    o.w = w1v * a.w + w2v * b.w;
    ((float4*)(out + (size_t)t * DM))[tid] = o;
}

// ---------------- launch -------------------------------------------------------
extern "C" void kernel_launch(void* const* d_in, const int* in_sizes, int n_in,
                              void* d_out, int out_size) {
    (void)in_sizes; (void)n_in; (void)out_size;
    const float* x  = (const float*)d_in[0];
    const float* rw = (const float*)d_in[1];
    const float* rb = (const float*)d_in[2];
    const float* w1 = (const float*)d_in[3];
    const float* b1 = (const float*)d_in[4];
    const float* w2 = (const float*)d_in[5];
    const float* b2 = (const float*)d_in[6];
    const float* wo = (const float*)d_in[7];
    const float* bo = (const float*)d_in[8];
    float* out = (float*)d_out;

    cudaFuncSetAttribute(ffn_in_h, cudaFuncAttributeMaxDynamicSharedMemorySize, FI_SMEM);

    init_kernel<<<1, 32>>>();
    router_prep<<<T_TOKENS / 8, 256>>>(x, rw, rb);
    finalize_kernel<<<1, 256>>>(out);
    prep_w12<<<dim3(64, 32, NE), 256>>>(w1, w2);
    prep_wo<<<dim3(256, 8, NE), 256>>>(wo);
    ffn_in_h<<<152, 512, FI_SMEM>>>(b1, b2);
    ffn_out_h<<<152, 512>>>(bo);
    combine_kernel<<<T_TOKENS, 256>>>(out);
}